// round 12
// baseline (speedup 1.0000x reference)
#include <cuda_runtime.h>
#include <cuda_fp16.h>
#include <cstdint>

#define NN   50000
#define EE   800000
#define EMB  16
#define KW   128
#define NCONV 4

// ---------------- device scratch (no cudaMalloc allowed) ----------------
__device__ __half  d_W[(size_t)EE * 256];     // per-edge W, [edge][o][i] fp16 (o=col-pair, i=row)
__device__ float   d_hA[NN * EMB];
__device__ float   d_hB[NN * EMB];
__device__ float   d_agg[NN * EMB];
__device__ float   d_cnt[NN];
__device__ __half2 d_k2p[8192];               // k2 fragments: [colQ][chunk16][lane][4]
__device__ __half2 d_k3p[16384];              // k3 fragments: [warp][chunk16][lane][4]
__device__ int     d_is64;

// ---------------- helpers ----------------
__device__ __forceinline__ void mma16816(float* c,
    uint32_t a0, uint32_t a1, uint32_t a2, uint32_t a3,
    uint32_t b0, uint32_t b1)
{
    asm volatile(
        "mma.sync.aligned.m16n8k16.row.col.f32.f16.f16.f32 "
        "{%0,%1,%2,%3},{%4,%5,%6,%7},{%8,%9},{%0,%1,%2,%3};\n"
        : "+f"(c[0]), "+f"(c[1]), "+f"(c[2]), "+f"(c[3])
        : "r"(a0), "r"(a1), "r"(a2), "r"(a3), "r"(b0), "r"(b1));
}

__device__ __forceinline__ void mma16808(float* c, uint32_t a0, uint32_t a1, uint32_t b0)
{
    asm volatile(
        "mma.sync.aligned.m16n8k8.row.col.f32.f16.f16.f32 "
        "{%0,%1,%2,%3},{%4,%5},{%6},{%0,%1,%2,%3};\n"
        : "+f"(c[0]), "+f"(c[1]), "+f"(c[2]), "+f"(c[3])
        : "r"(a0), "r"(a1), "r"(b0));
}

__device__ __forceinline__ void ldsm_x4(uint32_t* a, uint32_t saddr)
{
    asm volatile(
        "ldmatrix.sync.aligned.m8n8.x4.shared.b16 {%0,%1,%2,%3}, [%4];\n"
        : "=r"(a[0]), "=r"(a[1]), "=r"(a[2]), "=r"(a[3]) : "r"(saddr));
}

__device__ __forceinline__ void ldsm_x2(uint32_t* a, uint32_t saddr)
{
    asm volatile(
        "ldmatrix.sync.aligned.m8n8.x2.shared.b16 {%0,%1}, [%2];\n"
        : "=r"(a[0]), "=r"(a[1]) : "r"(saddr));
}

__device__ __forceinline__ void stcs_v4(void* p, uint32_t x, uint32_t y, uint32_t z, uint32_t w)
{
    asm volatile("st.global.cs.v4.b32 [%0], {%1,%2,%3,%4};\n"
                 :: "l"(p), "r"(x), "r"(y), "r"(z), "r"(w) : "memory");
}

// ---------------- kernels ----------------

__global__ void k_detect(const int* __restrict__ ei)
{
    __shared__ int anynz;
    if (threadIdx.x == 0) anynz = 0;
    __syncthreads();
    int v = ei[2 * threadIdx.x + 1];
    if (v != 0) atomicOr(&anynz, 1);
    __syncthreads();
    if (threadIdx.x == 0) d_is64 = (anynz == 0) ? 1 : 0;
}

// Fused setup: blocks [0,3125) do h0 init + agg/cnt zero; blocks [3125,3221)
// build the fragment-permuted fp16 B tables for layers 2 and 3.
__global__ void k_setup(const float* __restrict__ x,
                        const float* __restrict__ emb_w,
                        const float* __restrict__ emb_b,
                        const float* __restrict__ k2w,
                        const float* __restrict__ k3w)
{
    if (blockIdx.x < 3125) {
        int t = blockIdx.x * 256 + threadIdx.x;
        if (t >= NN * EMB) return;
        int n = t >> 4, o = t & 15;
        float v = emb_b[o];
        #pragma unroll
        for (int f = 0; f < 3; f++) v += x[n * 3 + f] * emb_w[f * EMB + o];
        d_hA[t]  = v;
        d_agg[t] = 0.f;
        if (o == 0) d_cnt[n] = 0.f;
        return;
    }
    int t = (blockIdx.x - 3125) * 256 + threadIdx.x;
    if (t < 8192) {            // stage-2 table: 4 colQ x 16 chunks x 32 lanes x 4
        int j = t & 3, l = (t >> 2) & 31, c = (t >> 7) & 15, cq = t >> 11;
        int q = c * 4 + j;                       // nt*16 + ks*2 + h
        int nt = q >> 4, ks = (q >> 1) & 7, h = q & 1;
        int g = l >> 2, tg = l & 3;
        int n = cq * 32 + nt * 8 + g;
        int k = ks * 16 + (tg & 1) * 8 + (h * 2 + (tg >> 1)) * 2;
        d_k2p[t] = __floats2half2_rn(k2w[k * KW + n], k2w[(k + 1) * KW + n]);
    } else if (t < 8192 + 16384) {  // stage-3 table: 8 warps x 16 chunks x 32 lanes x 4
        int t2 = t - 8192;
        int j = t2 & 3, l = (t2 >> 2) & 31, c = (t2 >> 7) & 15, w = t2 >> 11;
        int q = c * 4 + j;
        int nt = q >> 4, ks = (q >> 1) & 7, h = q & 1;
        int g = l >> 2, tg = l & 3;
        int n = w * 32 + nt * 8 + g;
        int k = (ks >> 1) * 32 + tg * 8 + ((ks & 1) * 2 + h) * 2;
        d_k3p[t2] = __floats2half2_rn(k3w[k * 256 + n], k3w[(k + 1) * 256 + n]);
    }
}

// Fused edge-MLP: 128 edges/block, all layers on tensor cores.
// Stage3 transposes W through smem (TWO 64-edge passes, confined to A1's
// region so live A2 rows are never clobbered) into [edge][o][i] DRAM layout.
__global__ __launch_bounds__(256, 2) void k_mlp(
    const void* __restrict__ ei,
    const float* __restrict__ ea,
    const float* __restrict__ k1w, const float* __restrict__ k1b,
    const float* __restrict__ k2b, const float* __restrict__ k3b)
{
    const int ST = KW + 8;                 // smem row stride in halves (272B, 16B-mult)
    extern __shared__ __half sm[];
    __half* A1 = sm;                       // e1: 128 x ST (K-permuted); later: W transpose tile
    __half* A2 = A1 + 128 * ST;            // e2: 128 x ST (K-permuted per 32-block)
    __half* EA = A2 + 128 * ST;            // ea fp16: 128 x 8

    const int tid  = threadIdx.x;
    const int warp = tid >> 5;
    const int lane = tid & 31;
    const int g    = lane >> 2;
    const int tg   = lane & 3;
    const long long ebase = (long long)blockIdx.x * 128;

    const uint32_t sA1 = (uint32_t)__cvta_generic_to_shared(A1);
    const uint32_t sA2 = (uint32_t)__cvta_generic_to_shared(A2);
    const uint32_t sEA = (uint32_t)__cvta_generic_to_shared(EA);
    const uint32_t lrow = (lane & 15);
    const uint32_t lcol = (lane >> 4) * 8;

    // ---- stage 0: ea -> fp16 smem tile [128 x 8]; fused edge count ----
    if (tid < 128) {
        const float* er = ea + (ebase + tid) * 6;
        float a0 = er[0], a1 = er[1], a2 = er[2], a3 = er[3], a4 = er[4], a5 = er[5];
        __half2* row = (__half2*)(EA + tid * 8);
        row[0] = __floats2half2_rn(a0, a1);
        row[1] = __floats2half2_rn(a2, a3);
        row[2] = __floats2half2_rn(a4, a5);
        row[3] = __floats2half2_rn(0.f, 0.f);
        long long dst;
        if (d_is64) dst = ((const long long*)ei)[EE + ebase + tid];
        else        dst = ((const int*)ei)[EE + ebase + tid];
        atomicAdd(&d_cnt[dst], 1.f);
    }

    // ---- stage 1: e1 = relu(ea @ k1_w + k1_b) via m16n8k8 -> permuted A1 ----
    {
        const int c0 = warp * 16;
        uint32_t B1[2];
        #pragma unroll
        for (int nt = 0; nt < 2; nt++) {
            int n  = c0 + nt * 8 + g;
            int k0 = tg * 2;
            float f0 = (k0     < 6) ? k1w[k0 * KW + n]       : 0.f;
            float f1 = (k0 + 1 < 6) ? k1w[(k0 + 1) * KW + n] : 0.f;
            __half2 hv = __floats2half2_rn(f0, f1);
            B1[nt] = *(uint32_t*)&hv;
        }
        float bias0 = k1b[c0 + tg * 2],     bias1 = k1b[c0 + tg * 2 + 1];
        float bias2 = k1b[c0 + 8 + tg * 2], bias3 = k1b[c0 + 8 + tg * 2 + 1];
        __syncthreads();   // EA tile ready

        #pragma unroll
        for (int rt = 0; rt < 8; rt++) {
            uint32_t a[2];
            ldsm_x2(a, sEA + (uint32_t)(rt * 16 + lrow) * 16);
            float acc0[4] = {0.f, 0.f, 0.f, 0.f};
            float acc1[4] = {0.f, 0.f, 0.f, 0.f};
            mma16808(acc0, a[0], a[1], B1[0]);
            mma16808(acc1, a[0], a[1], B1[1]);
            int r0 = rt * 16;
            __half2 q0 = __floats2half2_rn(
                fmaxf(acc0[0] + bias0, 0.f), fmaxf(acc0[1] + bias1, 0.f));
            __half2 q1 = __floats2half2_rn(
                fmaxf(acc1[0] + bias2, 0.f), fmaxf(acc1[1] + bias3, 0.f));
            *(uint2*)&A1[(r0 + g) * ST + c0 + tg * 4] =
                make_uint2(*(uint32_t*)&q0, *(uint32_t*)&q1);
            __half2 q2 = __floats2half2_rn(
                fmaxf(acc0[2] + bias0, 0.f), fmaxf(acc0[3] + bias1, 0.f));
            __half2 q3 = __floats2half2_rn(
                fmaxf(acc1[2] + bias2, 0.f), fmaxf(acc1[3] + bias3, 0.f));
            *(uint2*)&A1[(r0 + g + 8) * ST + c0 + tg * 4] =
                make_uint2(*(uint32_t*)&q2, *(uint32_t*)&q3);
        }
    }
    __syncthreads();

    // ---- stage 2: e2 = relu(e1 @ k2_w + k2_b), 2D warp tiling ----
    {
        const int colQ = warp & 3;         // 32-col quarter
        const int rowH = warp >> 2;        // 64-row half
        const int c0 = colQ * 32;
        uint32_t B2f[64];                  // [nt*16 + ks*2 + h]
        {
            const uint4* tp = ((const uint4*)d_k2p) + (colQ * 16) * 32 + lane;
            #pragma unroll
            for (int c = 0; c < 16; c++) {
                uint4 v = tp[c * 32];
                B2f[c * 4 + 0] = v.x; B2f[c * 4 + 1] = v.y;
                B2f[c * 4 + 2] = v.z; B2f[c * 4 + 3] = v.w;
            }
        }
        float biasA[4], biasB[4];
        #pragma unroll
        for (int nt = 0; nt < 4; nt++) {
            biasA[nt] = k2b[c0 + nt * 8 + tg * 2];
            biasB[nt] = k2b[c0 + nt * 8 + tg * 2 + 1];
        }

        #pragma unroll
        for (int rt = 0; rt < 4; rt++) {
            const int r0 = rowH * 64 + rt * 16;
            float acc[4][4];
            #pragma unroll
            for (int nt = 0; nt < 4; nt++)
                acc[nt][0] = acc[nt][1] = acc[nt][2] = acc[nt][3] = 0.f;
            #pragma unroll
            for (int ks = 0; ks < 8; ks++) {
                uint32_t a[4];
                ldsm_x4(a, sA1 + ((r0 + lrow) * ST + ks * 16 + lcol) * 2);
                #pragma unroll
                for (int nt = 0; nt < 4; nt++)
                    mma16816(acc[nt], a[0], a[1], a[2], a[3],
                             B2f[nt * 16 + ks * 2], B2f[nt * 16 + ks * 2 + 1]);
            }
            uint32_t p0[4], p1[4];
            #pragma unroll
            for (int nt = 0; nt < 4; nt++) {
                __half2 h0 = __floats2half2_rn(
                    fmaxf(acc[nt][0] + biasA[nt], 0.f), fmaxf(acc[nt][1] + biasB[nt], 0.f));
                __half2 h1 = __floats2half2_rn(
                    fmaxf(acc[nt][2] + biasA[nt], 0.f), fmaxf(acc[nt][3] + biasB[nt], 0.f));
                p0[nt] = *(uint32_t*)&h0;
                p1[nt] = *(uint32_t*)&h1;
            }
            *(uint4*)&A2[(r0 + g) * ST + c0 + tg * 8] =
                make_uint4(p0[0], p0[1], p0[2], p0[3]);
            *(uint4*)&A2[(r0 + g + 8) * ST + c0 + tg * 8] =
                make_uint4(p1[0], p1[1], p1[2], p1[3]);
        }
    }
    __syncthreads();

    // ---- stage 3: W = e2 @ k3_w + k3_b -> [e][o][i] via two 64-edge passes ----
    // Thread's half2 at (warp,g,tg,nt,row-half): o = (nt&1)*4+tg, i = warp*2+(nt>>1).
    // WT (in A1's region only): local edge el at word-offset el*132; word = o*16 + i.
    {
        const int c0 = warp * 32;
        uint32_t B3f[64];                  // [nt*16 + ks*2 + h]
        {
            const uint4* tp = ((const uint4*)d_k3p) + (warp * 16) * 32 + lane;
            #pragma unroll
            for (int c = 0; c < 16; c++) {
                uint4 v = tp[c * 32];
                B3f[c * 4 + 0] = v.x; B3f[c * 4 + 1] = v.y;
                B3f[c * 4 + 2] = v.z; B3f[c * 4 + 3] = v.w;
            }
        }
        float biasA[4], biasB[4];
        #pragma unroll
        for (int nt = 0; nt < 4; nt++) {
            biasA[nt] = k3b[c0 + nt * 8 + tg * 2];
            biasB[nt] = k3b[c0 + nt * 8 + tg * 2 + 1];
        }

        uint32_t* WT = (uint32_t*)A1;      // half2-word view, 132 words (528B) per edge
        #pragma unroll
        for (int pass = 0; pass < 2; pass++) {
            if (pass) __syncthreads();     // pass-0 copy-out done before WT reuse
            #pragma unroll
            for (int rt = 0; rt < 4; rt++) {
                const int r0 = pass * 64 + rt * 16;
                float acc[4][4];
                #pragma unroll
                for (int nt = 0; nt < 4; nt++)
                    acc[nt][0] = acc[nt][1] = acc[nt][2] = acc[nt][3] = 0.f;
                #pragma unroll
                for (int ks = 0; ks < 8; ks++) {
                    uint32_t a[4];
                    ldsm_x4(a, sA2 + ((r0 + lrow) * ST + ks * 16 + lcol) * 2);
                    #pragma unroll
                    for (int nt = 0; nt < 4; nt++)
                        mma16816(acc[nt], a[0], a[1], a[2], a[3],
                                 B3f[nt * 16 + ks * 2], B3f[nt * 16 + ks * 2 + 1]);
                }
                #pragma unroll
                for (int rh = 0; rh < 2; rh++) {
                    int rl = rt * 16 + g + rh * 8;   // local edge within pass (0..63)
                    __half2 a0 = __floats2half2_rn(acc[0][rh*2+0] + biasA[0], acc[0][rh*2+1] + biasB[0]);
                    __half2 a2 = __floats2half2_rn(acc[2][rh*2+0] + biasA[2], acc[2][rh*2+1] + biasB[2]);
                    __half2 a1 = __floats2half2_rn(acc[1][rh*2+0] + biasA[1], acc[1][rh*2+1] + biasB[1]);
                    __half2 a3 = __floats2half2_rn(acc[3][rh*2+0] + biasA[3], acc[3][rh*2+1] + biasB[3]);
                    int baseA = rl * 132 + tg * 16 + warp * 2;        // o=tg:   i=2w,2w+1
                    int baseB = rl * 132 + (tg + 4) * 16 + warp * 2;  // o=tg+4: i=2w,2w+1
                    *(uint2*)&WT[baseA] = make_uint2(*(uint32_t*)&a0, *(uint32_t*)&a2);
                    *(uint2*)&WT[baseB] = make_uint2(*(uint32_t*)&a1, *(uint32_t*)&a3);
                }
            }
            __syncthreads();
            // copy-out: 64 edges x 512B, coalesced 128-bit streaming stores
            {
                int el = tid >> 2, q = tid & 3;
                const uint4* srcv = (const uint4*)((const char*)A1 + el * 528 + q * 128);
                uint4* dstp = (uint4*)(d_W + (ebase + pass * 64 + el) * 256) + q * 8;
                #pragma unroll
                for (int k2 = 0; k2 < 8; k2++) {
                    uint4 v = srcv[k2];
                    stcs_v4(dstp + k2, v.x, v.y, v.z, v.w);
                }
            }
        }
    }
}

// msg = h[src] @ W_e ([o][i] layout) ; vector scatter-add into agg[dst]
__global__ void k_conv(const void* __restrict__ ei, const float* __restrict__ hin)
{
    long long e = (long long)blockIdx.x * 32 + (threadIdx.x >> 3);
    int o = threadIdx.x & 7;           // output half2 index (cols 2o, 2o+1)
    if (e >= EE) return;
    long long src, dst;
    if (d_is64) {
        const long long* p = (const long long*)ei;
        src = p[e]; dst = p[EE + e];
    } else {
        const int* p = (const int*)ei;
        src = p[e]; dst = p[EE + e];
    }
    const float4* hr4 = (const float4*)(hin + src * EMB);
    float4 h0 = hr4[0], h1 = hr4[1], h2 = hr4[2], h3 = hr4[3];
    float hr[16] = {h0.x,h0.y,h0.z,h0.w, h1.x,h1.y,h1.z,h1.w,
                    h2.x,h2.y,h2.z,h2.w, h3.x,h3.y,h3.z,h3.w};
    // contiguous 64B: thread o owns halves [o*32, o*32+32) = cols {2o,2o+1}, all i
    const uint4* wp = (const uint4*)(d_W + e * 256 + o * 32);
    uint4 w0 = __ldcs(wp), w1 = __ldcs(wp + 1), w2 = __ldcs(wp + 2), w3 = __ldcs(wp + 3);
    uint32_t wv[16] = {w0.x,w0.y,w0.z,w0.w, w1.x,w1.y,w1.z,w1.w,
                       w2.x,w2.y,w2.z,w2.w, w3.x,w3.y,w3.z,w3.w};
    float mx = 0.f, my = 0.f;
    #pragma unroll
    for (int i = 0; i < 16; i++) {
        float2 wf = __half22float2(*(__half2*)&wv[i]);
        mx = fmaf(hr[i], wf.x, mx);
        my = fmaf(hr[i], wf.y, my);
    }
    float* dp = &d_agg[dst * EMB + 2 * o];
    asm volatile("red.global.add.v2.f32 [%0], {%1,%2};\n"
                 :: "l"(dp), "f"(mx), "f"(my) : "memory");
}

// h_out = relu(agg/denom + h_in @ root_w + conv_b); zero agg for next round
__global__ void k_update(const float* __restrict__ hin, float* __restrict__ hout,
                         const float* __restrict__ root_w, const float* __restrict__ conv_b)
{
    int t = blockIdx.x * blockDim.x + threadIdx.x;
    if (t >= NN * EMB) return;
    int n = t >> 4, o = t & 15;
    float denom = fmaxf(d_cnt[n], 1.f);
    float v = d_agg[t] / denom;
    const float* hr = hin + n * EMB;
    #pragma unroll
    for (int i = 0; i < 16; i++) v = fmaf(hr[i], root_w[i * EMB + o], v);
    v += conv_b[o];
    hout[t] = fmaxf(v, 0.f);
    d_agg[t] = 0.f;
}

__global__ void k_out(const float* __restrict__ hin,
                      const float* __restrict__ inv_w, const float* __restrict__ inv_b,
                      float* __restrict__ out)
{
    int t = blockIdx.x * blockDim.x + threadIdx.x;
    if (t >= NN * 3) return;
    int n = t / 3, f = t % 3;
    float v = inv_b[f];
    const float* hr = hin + n * EMB;
    #pragma unroll
    for (int i = 0; i < 16; i++) v = fmaf(hr[i], inv_w[i * 3 + f], v);
    out[t] = v;
}

// ---------------- launcher ----------------
extern "C" void kernel_launch(void* const* d_in, const int* in_sizes, int n_in,
                              void* d_out, int out_size)
{
    const float* x      = (const float*)d_in[0];
    const void*  ei     = d_in[1];
    const float* ea     = (const float*)d_in[2];
    const float* emb_w  = (const float*)d_in[3];
    const float* emb_b  = (const float*)d_in[4];
    const float* k1_w   = (const float*)d_in[5];
    const float* k1_b   = (const float*)d_in[6];
    const float* k2_w   = (const float*)d_in[7];
    const float* k2_b   = (const float*)d_in[8];
    const float* k3_w   = (const float*)d_in[9];
    const float* k3_b   = (const float*)d_in[10];
    const float* root_w = (const float*)d_in[11];
    const float* conv_b = (const float*)d_in[12];
    const float* inv_w  = (const float*)d_in[13];
    const float* inv_b  = (const float*)d_in[14];
    float* out = (float*)d_out;

    const int ST = KW + 8;
    const int smemBytes = (2 * 128 * ST + 128 * 8) * (int)sizeof(__half);  // 71680
    cudaFuncSetAttribute(k_mlp, cudaFuncAttributeMaxDynamicSharedMemorySize, smemBytes);

    static float* hA = nullptr;
    static float* hB = nullptr;
    if (!hA) {
        cudaGetSymbolAddress((void**)&hA, d_hA);
        cudaGetSymbolAddress((void**)&hB, d_hB);
    }

    // Launch order: detect(1), setup(2), mlp(3), conv1(4) — k_conv stays in the
    // ncu-profiled slot to verify the wavefront-amplification fix.
    k_detect<<<1, 256>>>((const int*)ei);
    k_setup<<<3125 + 96, 256>>>(x, emb_w, emb_b, k2_w, k3_w);
    k_mlp<<<EE / 128, 256, smemBytes>>>(ei, ea, k1_w, k1_b, k2_b, k3_b);

    float* hin  = hA;
    float* hout = hB;
    for (int it = 0; it < NCONV; it++) {
        k_conv<<<EE / 32, 256>>>(ei, hin);
        k_update<<<(NN * EMB + 255) / 256, 256>>>(hin, hout, root_w, conv_b);
        float* tmp = hin; hin = hout; hout = tmp;
    }
    k_out<<<(NN * 3 + 255) / 256, 256>>>(hin, inv_w, inv_b, out);
}

// round 13
// speedup vs baseline: 1.2176x; 1.2176x over previous
#include <cuda_runtime.h>
#include <cuda_fp16.h>
#include <cstdint>

#define NN   50000
#define EE   800000
#define EMB  16
#define KW   128
#define NCONV 4

// ---------------- device scratch (no cudaMalloc allowed) ----------------
// d_W per-edge layout (128 half2-words/edge): word w = k*32 + o*4 + j holds
// W[i][2o..2o+1] with i = k*4 + j  -> conv thread o reads uint4s {k*8+o}.
__device__ __half  d_W[(size_t)EE * 256];
__device__ float   d_hA[NN * EMB];
__device__ float   d_hB[NN * EMB];
__device__ float   d_agg[NN * EMB];
__device__ float   d_cnt[NN];
__device__ __half2 d_k2p[8192];               // k2 fragments: [colQ][chunk16][lane][4]
__device__ __half2 d_k3p[16384];              // k3 fragments: [warp][chunk16][lane][4]
__device__ int     d_is64;

// ---------------- helpers ----------------
__device__ __forceinline__ void mma16816(float* c,
    uint32_t a0, uint32_t a1, uint32_t a2, uint32_t a3,
    uint32_t b0, uint32_t b1)
{
    asm volatile(
        "mma.sync.aligned.m16n8k16.row.col.f32.f16.f16.f32 "
        "{%0,%1,%2,%3},{%4,%5,%6,%7},{%8,%9},{%0,%1,%2,%3};\n"
        : "+f"(c[0]), "+f"(c[1]), "+f"(c[2]), "+f"(c[3])
        : "r"(a0), "r"(a1), "r"(a2), "r"(a3), "r"(b0), "r"(b1));
}

__device__ __forceinline__ void mma16808(float* c, uint32_t a0, uint32_t a1, uint32_t b0)
{
    asm volatile(
        "mma.sync.aligned.m16n8k8.row.col.f32.f16.f16.f32 "
        "{%0,%1,%2,%3},{%4,%5},{%6},{%0,%1,%2,%3};\n"
        : "+f"(c[0]), "+f"(c[1]), "+f"(c[2]), "+f"(c[3])
        : "r"(a0), "r"(a1), "r"(b0));
}

__device__ __forceinline__ void ldsm_x4(uint32_t* a, uint32_t saddr)
{
    asm volatile(
        "ldmatrix.sync.aligned.m8n8.x4.shared.b16 {%0,%1,%2,%3}, [%4];\n"
        : "=r"(a[0]), "=r"(a[1]), "=r"(a[2]), "=r"(a[3]) : "r"(saddr));
}

__device__ __forceinline__ void ldsm_x2(uint32_t* a, uint32_t saddr)
{
    asm volatile(
        "ldmatrix.sync.aligned.m8n8.x2.shared.b16 {%0,%1}, [%2];\n"
        : "=r"(a[0]), "=r"(a[1]) : "r"(saddr));
}

__device__ __forceinline__ void stcs_v2(void* p, uint32_t x, uint32_t y)
{
    asm volatile("st.global.cs.v2.b32 [%0], {%1,%2};\n"
                 :: "l"(p), "r"(x), "r"(y) : "memory");
}

// ---------------- kernels ----------------

__global__ void k_detect(const int* __restrict__ ei)
{
    __shared__ int anynz;
    if (threadIdx.x == 0) anynz = 0;
    __syncthreads();
    int v = ei[2 * threadIdx.x + 1];
    if (v != 0) atomicOr(&anynz, 1);
    __syncthreads();
    if (threadIdx.x == 0) d_is64 = (anynz == 0) ? 1 : 0;
}

// Fused setup: blocks [0,3125) do h0 init + agg/cnt zero; blocks [3125,3221)
// build the fragment-permuted fp16 B tables for layers 2 and 3.
__global__ void k_setup(const float* __restrict__ x,
                        const float* __restrict__ emb_w,
                        const float* __restrict__ emb_b,
                        const float* __restrict__ k2w,
                        const float* __restrict__ k3w)
{
    if (blockIdx.x < 3125) {
        int t = blockIdx.x * 256 + threadIdx.x;
        if (t >= NN * EMB) return;
        int n = t >> 4, o = t & 15;
        float v = emb_b[o];
        #pragma unroll
        for (int f = 0; f < 3; f++) v += x[n * 3 + f] * emb_w[f * EMB + o];
        d_hA[t]  = v;
        d_agg[t] = 0.f;
        if (o == 0) d_cnt[n] = 0.f;
        return;
    }
    int t = (blockIdx.x - 3125) * 256 + threadIdx.x;
    if (t < 8192) {            // stage-2 table: 4 colQ x 16 chunks x 32 lanes x 4
        int j = t & 3, l = (t >> 2) & 31, c = (t >> 7) & 15, cq = t >> 11;
        int q = c * 4 + j;                       // nt*16 + ks*2 + h
        int nt = q >> 4, ks = (q >> 1) & 7, h = q & 1;
        int g = l >> 2, tg = l & 3;
        int n = cq * 32 + nt * 8 + g;
        int k = ks * 16 + (tg & 1) * 8 + (h * 2 + (tg >> 1)) * 2;
        d_k2p[t] = __floats2half2_rn(k2w[k * KW + n], k2w[(k + 1) * KW + n]);
    } else if (t < 8192 + 16384) {  // stage-3 table: 8 warps x 16 chunks x 32 lanes x 4
        int t2 = t - 8192;
        int j = t2 & 3, l = (t2 >> 2) & 31, c = (t2 >> 7) & 15, w = t2 >> 11;
        int q = c * 4 + j;
        int nt = q >> 4, ks = (q >> 1) & 7, h = q & 1;
        int g = l >> 2, tg = l & 3;
        int n = w * 32 + nt * 8 + g;
        int k = (ks >> 1) * 32 + tg * 8 + ((ks & 1) * 2 + h) * 2;
        d_k3p[t2] = __floats2half2_rn(k3w[k * 256 + n], k3w[(k + 1) * 256 + n]);
    }
}

// Fused edge-MLP: 128 edges/block, all layers on tensor cores.
// Stage3 stores W directly from registers into the conv-coalesced
// [k][o] interleaved layout (2x STG.64.cs per row-half, no smem round-trip).
__global__ __launch_bounds__(256, 2) void k_mlp(
    const void* __restrict__ ei,
    const float* __restrict__ ea,
    const float* __restrict__ k1w, const float* __restrict__ k1b,
    const float* __restrict__ k2b, const float* __restrict__ k3b)
{
    const int ST = KW + 8;                 // smem row stride in halves (272B, 16B-mult)
    extern __shared__ __half sm[];
    __half* A1 = sm;                       // e1: 128 x ST (K-permuted per 16-block)
    __half* A2 = A1 + 128 * ST;            // e2: 128 x ST (K-permuted per 32-block)
    __half* EA = A2 + 128 * ST;            // ea fp16: 128 x 8

    const int tid  = threadIdx.x;
    const int warp = tid >> 5;
    const int lane = tid & 31;
    const int g    = lane >> 2;
    const int tg   = lane & 3;
    const long long ebase = (long long)blockIdx.x * 128;

    const uint32_t sA1 = (uint32_t)__cvta_generic_to_shared(A1);
    const uint32_t sA2 = (uint32_t)__cvta_generic_to_shared(A2);
    const uint32_t sEA = (uint32_t)__cvta_generic_to_shared(EA);
    const uint32_t lrow = (lane & 15);
    const uint32_t lcol = (lane >> 4) * 8;

    // ---- stage 0: ea -> fp16 smem tile [128 x 8]; fused edge count ----
    if (tid < 128) {
        const float* er = ea + (ebase + tid) * 6;
        float a0 = er[0], a1 = er[1], a2 = er[2], a3 = er[3], a4 = er[4], a5 = er[5];
        __half2* row = (__half2*)(EA + tid * 8);
        row[0] = __floats2half2_rn(a0, a1);
        row[1] = __floats2half2_rn(a2, a3);
        row[2] = __floats2half2_rn(a4, a5);
        row[3] = __floats2half2_rn(0.f, 0.f);
        long long dst;
        if (d_is64) dst = ((const long long*)ei)[EE + ebase + tid];
        else        dst = ((const int*)ei)[EE + ebase + tid];
        atomicAdd(&d_cnt[dst], 1.f);
    }

    // ---- stage 1: e1 = relu(ea @ k1_w + k1_b) via m16n8k8 -> permuted A1 ----
    {
        const int c0 = warp * 16;
        uint32_t B1[2];
        #pragma unroll
        for (int nt = 0; nt < 2; nt++) {
            int n  = c0 + nt * 8 + g;
            int k0 = tg * 2;
            float f0 = (k0     < 6) ? k1w[k0 * KW + n]       : 0.f;
            float f1 = (k0 + 1 < 6) ? k1w[(k0 + 1) * KW + n] : 0.f;
            __half2 hv = __floats2half2_rn(f0, f1);
            B1[nt] = *(uint32_t*)&hv;
        }
        float bias0 = k1b[c0 + tg * 2],     bias1 = k1b[c0 + tg * 2 + 1];
        float bias2 = k1b[c0 + 8 + tg * 2], bias3 = k1b[c0 + 8 + tg * 2 + 1];
        __syncthreads();   // EA tile ready

        #pragma unroll
        for (int rt = 0; rt < 8; rt++) {
            uint32_t a[2];
            ldsm_x2(a, sEA + (uint32_t)(rt * 16 + lrow) * 16);
            float acc0[4] = {0.f, 0.f, 0.f, 0.f};
            float acc1[4] = {0.f, 0.f, 0.f, 0.f};
            mma16808(acc0, a[0], a[1], B1[0]);
            mma16808(acc1, a[0], a[1], B1[1]);
            int r0 = rt * 16;
            __half2 q0 = __floats2half2_rn(
                fmaxf(acc0[0] + bias0, 0.f), fmaxf(acc0[1] + bias1, 0.f));
            __half2 q1 = __floats2half2_rn(
                fmaxf(acc1[0] + bias2, 0.f), fmaxf(acc1[1] + bias3, 0.f));
            *(uint2*)&A1[(r0 + g) * ST + c0 + tg * 4] =
                make_uint2(*(uint32_t*)&q0, *(uint32_t*)&q1);
            __half2 q2 = __floats2half2_rn(
                fmaxf(acc0[2] + bias0, 0.f), fmaxf(acc0[3] + bias1, 0.f));
            __half2 q3 = __floats2half2_rn(
                fmaxf(acc1[2] + bias2, 0.f), fmaxf(acc1[3] + bias3, 0.f));
            *(uint2*)&A1[(r0 + g + 8) * ST + c0 + tg * 4] =
                make_uint2(*(uint32_t*)&q2, *(uint32_t*)&q3);
        }
    }
    __syncthreads();

    // ---- stage 2: e2 = relu(e1 @ k2_w + k2_b), 2D warp tiling ----
    {
        const int colQ = warp & 3;         // 32-col quarter
        const int rowH = warp >> 2;        // 64-row half
        const int c0 = colQ * 32;
        uint32_t B2f[64];                  // [nt*16 + ks*2 + h]
        {
            const uint4* tp = ((const uint4*)d_k2p) + (colQ * 16) * 32 + lane;
            #pragma unroll
            for (int c = 0; c < 16; c++) {
                uint4 v = tp[c * 32];
                B2f[c * 4 + 0] = v.x; B2f[c * 4 + 1] = v.y;
                B2f[c * 4 + 2] = v.z; B2f[c * 4 + 3] = v.w;
            }
        }
        float biasA[4], biasB[4];
        #pragma unroll
        for (int nt = 0; nt < 4; nt++) {
            biasA[nt] = k2b[c0 + nt * 8 + tg * 2];
            biasB[nt] = k2b[c0 + nt * 8 + tg * 2 + 1];
        }

        #pragma unroll
        for (int rt = 0; rt < 4; rt++) {
            const int r0 = rowH * 64 + rt * 16;
            float acc[4][4];
            #pragma unroll
            for (int nt = 0; nt < 4; nt++)
                acc[nt][0] = acc[nt][1] = acc[nt][2] = acc[nt][3] = 0.f;
            #pragma unroll
            for (int ks = 0; ks < 8; ks++) {
                uint32_t a[4];
                ldsm_x4(a, sA1 + ((r0 + lrow) * ST + ks * 16 + lcol) * 2);
                #pragma unroll
                for (int nt = 0; nt < 4; nt++)
                    mma16816(acc[nt], a[0], a[1], a[2], a[3],
                             B2f[nt * 16 + ks * 2], B2f[nt * 16 + ks * 2 + 1]);
            }
            uint32_t p0[4], p1[4];
            #pragma unroll
            for (int nt = 0; nt < 4; nt++) {
                __half2 h0 = __floats2half2_rn(
                    fmaxf(acc[nt][0] + biasA[nt], 0.f), fmaxf(acc[nt][1] + biasB[nt], 0.f));
                __half2 h1 = __floats2half2_rn(
                    fmaxf(acc[nt][2] + biasA[nt], 0.f), fmaxf(acc[nt][3] + biasB[nt], 0.f));
                p0[nt] = *(uint32_t*)&h0;
                p1[nt] = *(uint32_t*)&h1;
            }
            *(uint4*)&A2[(r0 + g) * ST + c0 + tg * 8] =
                make_uint4(p0[0], p0[1], p0[2], p0[3]);
            *(uint4*)&A2[(r0 + g + 8) * ST + c0 + tg * 8] =
                make_uint4(p1[0], p1[1], p1[2], p1[3]);
        }
    }
    __syncthreads();

    // ---- stage 3: W = e2 @ k3_w + k3_b -> conv-coalesced [k][o] layout ----
    // Thread's half2 (nt, row-half): o = (nt&1)*4+tg, i = warp*2+(nt>>1).
    // Store word(i,o) = (i>>2)*32 + o*4 + (i&3). Pairs {nt0,nt2}, {nt1,nt3}
    // are word-adjacent -> 2x STG.64.cs per row-half.
    {
        const int c0 = warp * 32;
        uint32_t B3f[64];                  // [nt*16 + ks*2 + h]
        {
            const uint4* tp = ((const uint4*)d_k3p) + (warp * 16) * 32 + lane;
            #pragma unroll
            for (int c = 0; c < 16; c++) {
                uint4 v = tp[c * 32];
                B3f[c * 4 + 0] = v.x; B3f[c * 4 + 1] = v.y;
                B3f[c * 4 + 2] = v.z; B3f[c * 4 + 3] = v.w;
            }
        }
        float biasA[4], biasB[4];
        #pragma unroll
        for (int nt = 0; nt < 4; nt++) {
            biasA[nt] = k3b[c0 + nt * 8 + tg * 2];
            biasB[nt] = k3b[c0 + nt * 8 + tg * 2 + 1];
        }

        const int W0 = (warp >> 1) * 32 + tg * 4 + (warp & 1) * 2;        // o=tg
        const int W1 = (warp >> 1) * 32 + (tg + 4) * 4 + (warp & 1) * 2;  // o=tg+4

        #pragma unroll
        for (int rt = 0; rt < 8; rt++) {
            const int r0 = rt * 16;
            float acc[4][4];
            #pragma unroll
            for (int nt = 0; nt < 4; nt++)
                acc[nt][0] = acc[nt][1] = acc[nt][2] = acc[nt][3] = 0.f;
            #pragma unroll
            for (int ks = 0; ks < 8; ks++) {
                uint32_t a[4];
                ldsm_x4(a, sA2 + ((r0 + lrow) * ST + ks * 16 + lcol) * 2);
                #pragma unroll
                for (int nt = 0; nt < 4; nt++)
                    mma16816(acc[nt], a[0], a[1], a[2], a[3],
                             B3f[nt * 16 + ks * 2], B3f[nt * 16 + ks * 2 + 1]);
            }
            uint32_t p0[4], p1[4];
            #pragma unroll
            for (int nt = 0; nt < 4; nt++) {
                __half2 h0 = __floats2half2_rn(acc[nt][0] + biasA[nt], acc[nt][1] + biasB[nt]);
                __half2 h1 = __floats2half2_rn(acc[nt][2] + biasA[nt], acc[nt][3] + biasB[nt]);
                p0[nt] = *(uint32_t*)&h0;
                p1[nt] = *(uint32_t*)&h1;
            }
            uint32_t* Wp0 = (uint32_t*)(d_W + (ebase + r0 + g) * 256);
            uint32_t* Wp1 = (uint32_t*)(d_W + (ebase + r0 + g + 8) * 256);
            stcs_v2(&Wp0[W0], p0[0], p0[2]);
            stcs_v2(&Wp0[W1], p0[1], p0[3]);
            stcs_v2(&Wp1[W0], p1[0], p1[2]);
            stcs_v2(&Wp1[W1], p1[1], p1[3]);
        }
    }
}

// msg = h[src] @ W_e ([k][o] layout) ; vector scatter-add into agg[dst]
__global__ void k_conv(const void* __restrict__ ei, const float* __restrict__ hin)
{
    long long e = (long long)blockIdx.x * 32 + (threadIdx.x >> 3);
    int o = threadIdx.x & 7;           // output half2 index (cols 2o, 2o+1)
    if (e >= EE) return;
    long long src, dst;
    if (d_is64) {
        const long long* p = (const long long*)ei;
        src = p[e]; dst = p[EE + e];
    } else {
        const int* p = (const int*)ei;
        src = p[e]; dst = p[EE + e];
    }
    const float4* hr4 = (const float4*)(hin + src * EMB);
    float4 h0 = hr4[0], h1 = hr4[1], h2 = hr4[2], h3 = hr4[3];
    float hr[16] = {h0.x,h0.y,h0.z,h0.w, h1.x,h1.y,h1.z,h1.w,
                    h2.x,h2.y,h2.z,h2.w, h3.x,h3.y,h3.z,h3.w};
    // uint4 #k at e*16 + k*8 + o: per instruction the warp (4 edges x 8 o)
    // reads 4 complete 128B lines -> no wavefront amplification.
    const uint4* wp = (const uint4*)(d_W + e * 256);
    uint4 w0 = __ldcs(wp + o), w1 = __ldcs(wp + 8 + o),
          w2 = __ldcs(wp + 16 + o), w3 = __ldcs(wp + 24 + o);
    uint32_t wv[16] = {w0.x,w0.y,w0.z,w0.w, w1.x,w1.y,w1.z,w1.w,
                       w2.x,w2.y,w2.z,w2.w, w3.x,w3.y,w3.z,w3.w};
    float mx = 0.f, my = 0.f;
    #pragma unroll
    for (int i = 0; i < 16; i++) {
        float2 wf = __half22float2(*(__half2*)&wv[i]);   // wv[i] = W[i][2o..2o+1]
        mx = fmaf(hr[i], wf.x, mx);
        my = fmaf(hr[i], wf.y, my);
    }
    float* dp = &d_agg[dst * EMB + 2 * o];
    asm volatile("red.global.add.v2.f32 [%0], {%1,%2};\n"
                 :: "l"(dp), "f"(mx), "f"(my) : "memory");
}

// h_out = relu(agg/denom + h_in @ root_w + conv_b); zero agg for next round
__global__ void k_update(const float* __restrict__ hin, float* __restrict__ hout,
                         const float* __restrict__ root_w, const float* __restrict__ conv_b)
{
    int t = blockIdx.x * blockDim.x + threadIdx.x;
    if (t >= NN * EMB) return;
    int n = t >> 4, o = t & 15;
    float denom = fmaxf(d_cnt[n], 1.f);
    float v = d_agg[t] / denom;
    const float* hr = hin + n * EMB;
    #pragma unroll
    for (int i = 0; i < 16; i++) v = fmaf(hr[i], root_w[i * EMB + o], v);
    v += conv_b[o];
    hout[t] = fmaxf(v, 0.f);
    d_agg[t] = 0.f;
}

__global__ void k_out(const float* __restrict__ hin,
                      const float* __restrict__ inv_w, const float* __restrict__ inv_b,
                      float* __restrict__ out)
{
    int t = blockIdx.x * blockDim.x + threadIdx.x;
    if (t >= NN * 3) return;
    int n = t / 3, f = t % 3;
    float v = inv_b[f];
    const float* hr = hin + n * EMB;
    #pragma unroll
    for (int i = 0; i < 16; i++) v = fmaf(hr[i], inv_w[i * 3 + f], v);
    out[t] = v;
}

// ---------------- launcher ----------------
extern "C" void kernel_launch(void* const* d_in, const int* in_sizes, int n_in,
                              void* d_out, int out_size)
{
    const float* x      = (const float*)d_in[0];
    const void*  ei     = d_in[1];
    const float* ea     = (const float*)d_in[2];
    const float* emb_w  = (const float*)d_in[3];
    const float* emb_b  = (const float*)d_in[4];
    const float* k1_w   = (const float*)d_in[5];
    const float* k1_b   = (const float*)d_in[6];
    const float* k2_w   = (const float*)d_in[7];
    const float* k2_b   = (const float*)d_in[8];
    const float* k3_w   = (const float*)d_in[9];
    const float* k3_b   = (const float*)d_in[10];
    const float* root_w = (const float*)d_in[11];
    const float* conv_b = (const float*)d_in[12];
    const float* inv_w  = (const float*)d_in[13];
    const float* inv_b  = (const float*)d_in[14];
    float* out = (float*)d_out;

    const int ST = KW + 8;
    const int smemBytes = (2 * 128 * ST + 128 * 8) * (int)sizeof(__half);  // 71680
    cudaFuncSetAttribute(k_mlp, cudaFuncAttributeMaxDynamicSharedMemorySize, smemBytes);

    static float* hA = nullptr;
    static float* hB = nullptr;
    if (!hA) {
        cudaGetSymbolAddress((void**)&hA, d_hA);
        cudaGetSymbolAddress((void**)&hB, d_hB);
    }

    // Launch order: detect(1), setup(2), mlp(3), conv1(4) — k_conv stays in the
    // ncu-profiled slot to verify the coalescing fix.
    k_detect<<<1, 256>>>((const int*)ei);
    k_setup<<<3125 + 96, 256>>>(x, emb_w, emb_b, k2_w, k3_w);
    k_mlp<<<EE / 128, 256, smemBytes>>>(ei, ea, k1_w, k1_b, k2_b, k3_b);

    float* hin  = hA;
    float* hout = hB;
    for (int it = 0; it < NCONV; it++) {
        k_conv<<<EE / 32, 256>>>(ei, hin);
        k_update<<<(NN * EMB + 255) / 256, 256>>>(hin, hout, root_w, conv_b);
        float* tmp = hin; hin = hout; hout = tmp;
    }
    k_out<<<(NN * 3 + 255) / 256, 256>>>(hin, inv_w, inv_b, out);
}

// round 14
// speedup vs baseline: 1.2258x; 1.0068x over previous
#include <cuda_runtime.h>
#include <cuda_fp16.h>
#include <cstdint>

#define NN   50000
#define EE   800000
#define EMB  16
#define KW   128
#define NCONV 4

// ---------------- device scratch (no cudaMalloc allowed) ----------------
// d_W per-edge layout (128 half2-words/edge): word w = k*32 + o*4 + j holds
// W[i][2o..2o+1] with i = k*4 + j  -> conv thread o reads uint4s {k*8+o}.
__device__ __half  d_W[(size_t)EE * 256];
__device__ float   d_hA[NN * EMB];
__device__ float   d_hB[NN * EMB];
__device__ float   d_agg[NN * EMB];
__device__ float   d_cnt[NN];
__device__ __half2 d_k2p[8192];               // k2 fragments: [colQ][chunk16][lane][4]
__device__ __half2 d_k3p[16384];              // k3 fragments: [warp][chunk16][lane][4]
__device__ int     d_is64;

// ---------------- helpers ----------------
__device__ __forceinline__ void mma16816(float* c,
    uint32_t a0, uint32_t a1, uint32_t a2, uint32_t a3,
    uint32_t b0, uint32_t b1)
{
    asm volatile(
        "mma.sync.aligned.m16n8k16.row.col.f32.f16.f16.f32 "
        "{%0,%1,%2,%3},{%4,%5,%6,%7},{%8,%9},{%0,%1,%2,%3};\n"
        : "+f"(c[0]), "+f"(c[1]), "+f"(c[2]), "+f"(c[3])
        : "r"(a0), "r"(a1), "r"(a2), "r"(a3), "r"(b0), "r"(b1));
}

__device__ __forceinline__ void mma16808(float* c, uint32_t a0, uint32_t a1, uint32_t b0)
{
    asm volatile(
        "mma.sync.aligned.m16n8k8.row.col.f32.f16.f16.f32 "
        "{%0,%1,%2,%3},{%4,%5},{%6},{%0,%1,%2,%3};\n"
        : "+f"(c[0]), "+f"(c[1]), "+f"(c[2]), "+f"(c[3])
        : "r"(a0), "r"(a1), "r"(b0));
}

__device__ __forceinline__ void ldsm_x4(uint32_t* a, uint32_t saddr)
{
    asm volatile(
        "ldmatrix.sync.aligned.m8n8.x4.shared.b16 {%0,%1,%2,%3}, [%4];\n"
        : "=r"(a[0]), "=r"(a[1]), "=r"(a[2]), "=r"(a[3]) : "r"(saddr));
}

__device__ __forceinline__ void ldsm_x2(uint32_t* a, uint32_t saddr)
{
    asm volatile(
        "ldmatrix.sync.aligned.m8n8.x2.shared.b16 {%0,%1}, [%2];\n"
        : "=r"(a[0]), "=r"(a[1]) : "r"(saddr));
}

__device__ __forceinline__ void stcs_v2(void* p, uint32_t x, uint32_t y)
{
    asm volatile("st.global.cs.v2.b32 [%0], {%1,%2};\n"
                 :: "l"(p), "r"(x), "r"(y) : "memory");
}

// ---------------- kernels ----------------

// Fused setup: blocks [0,3125) h0 init + zero agg/cnt; blocks [3125,3221)
// B tables; block 3221 edge-index dtype detection.
__global__ void k_setup(const int* __restrict__ ei,
                        const float* __restrict__ x,
                        const float* __restrict__ emb_w,
                        const float* __restrict__ emb_b,
                        const float* __restrict__ k2w,
                        const float* __restrict__ k3w)
{
    if (blockIdx.x < 3125) {
        int t = blockIdx.x * 256 + threadIdx.x;
        if (t >= NN * EMB) return;
        int n = t >> 4, o = t & 15;
        float v = emb_b[o];
        #pragma unroll
        for (int f = 0; f < 3; f++) v += x[n * 3 + f] * emb_w[f * EMB + o];
        d_hA[t]  = v;
        d_agg[t] = 0.f;
        if (o == 0) d_cnt[n] = 0.f;
        return;
    }
    if (blockIdx.x == 3125 + 96) {      // dtype detect
        __shared__ int anynz;
        if (threadIdx.x == 0) anynz = 0;
        __syncthreads();
        int v = ei[2 * threadIdx.x + 1];
        if (v != 0) atomicOr(&anynz, 1);
        __syncthreads();
        if (threadIdx.x == 0) d_is64 = (anynz == 0) ? 1 : 0;
        return;
    }
    int t = (blockIdx.x - 3125) * 256 + threadIdx.x;
    if (t < 8192) {            // stage-2 table: 4 colQ x 16 chunks x 32 lanes x 4
        int j = t & 3, l = (t >> 2) & 31, c = (t >> 7) & 15, cq = t >> 11;
        int q = c * 4 + j;                       // nt*16 + ks*2 + h
        int nt = q >> 4, ks = (q >> 1) & 7, h = q & 1;
        int g = l >> 2, tg = l & 3;
        int n = cq * 32 + nt * 8 + g;
        int k = ks * 16 + (tg & 1) * 8 + (h * 2 + (tg >> 1)) * 2;
        d_k2p[t] = __floats2half2_rn(k2w[k * KW + n], k2w[(k + 1) * KW + n]);
    } else if (t < 8192 + 16384) {  // stage-3 table: 8 warps x 16 chunks x 32 lanes x 4
        int t2 = t - 8192;
        int j = t2 & 3, l = (t2 >> 2) & 31, c = (t2 >> 7) & 15, w = t2 >> 11;
        int q = c * 4 + j;
        int nt = q >> 4, ks = (q >> 1) & 7, h = q & 1;
        int g = l >> 2, tg = l & 3;
        int n = w * 32 + nt * 8 + g;
        int k = (ks >> 1) * 32 + tg * 8 + ((ks & 1) * 2 + h) * 2;
        d_k3p[t2] = __floats2half2_rn(k3w[k * 256 + n], k3w[(k + 1) * 256 + n]);
    }
}

// Fused edge-MLP: 128 edges/block, all layers on tensor cores.
// Stage3 stores W directly into the conv-coalesced [k][o] layout.
__global__ __launch_bounds__(256, 2) void k_mlp(
    const void* __restrict__ ei,
    const float* __restrict__ ea,
    const float* __restrict__ k1w, const float* __restrict__ k1b,
    const float* __restrict__ k2b, const float* __restrict__ k3b)
{
    const int ST = KW + 8;                 // smem row stride in halves (272B, 16B-mult)
    extern __shared__ __half sm[];
    __half* A1 = sm;                       // e1: 128 x ST (K-permuted per 16-block)
    __half* A2 = A1 + 128 * ST;            // e2: 128 x ST (K-permuted per 32-block)
    __half* EA = A2 + 128 * ST;            // ea fp16: 128 x 8

    const int tid  = threadIdx.x;
    const int warp = tid >> 5;
    const int lane = tid & 31;
    const int g    = lane >> 2;
    const int tg   = lane & 3;
    const long long ebase = (long long)blockIdx.x * 128;

    const uint32_t sA1 = (uint32_t)__cvta_generic_to_shared(A1);
    const uint32_t sA2 = (uint32_t)__cvta_generic_to_shared(A2);
    const uint32_t sEA = (uint32_t)__cvta_generic_to_shared(EA);
    const uint32_t lrow = (lane & 15);
    const uint32_t lcol = (lane >> 4) * 8;

    // ---- stage 0: ea -> fp16 smem tile [128 x 8]; fused edge count ----
    if (tid < 128) {
        const float* er = ea + (ebase + tid) * 6;
        float a0 = er[0], a1 = er[1], a2 = er[2], a3 = er[3], a4 = er[4], a5 = er[5];
        __half2* row = (__half2*)(EA + tid * 8);
        row[0] = __floats2half2_rn(a0, a1);
        row[1] = __floats2half2_rn(a2, a3);
        row[2] = __floats2half2_rn(a4, a5);
        row[3] = __floats2half2_rn(0.f, 0.f);
        long long dst;
        if (d_is64) dst = ((const long long*)ei)[EE + ebase + tid];
        else        dst = ((const int*)ei)[EE + ebase + tid];
        atomicAdd(&d_cnt[dst], 1.f);
    }

    // ---- stage 1: e1 = relu(ea @ k1_w + k1_b) via m16n8k8 -> permuted A1 ----
    {
        const int c0 = warp * 16;
        uint32_t B1[2];
        #pragma unroll
        for (int nt = 0; nt < 2; nt++) {
            int n  = c0 + nt * 8 + g;
            int k0 = tg * 2;
            float f0 = (k0     < 6) ? k1w[k0 * KW + n]       : 0.f;
            float f1 = (k0 + 1 < 6) ? k1w[(k0 + 1) * KW + n] : 0.f;
            __half2 hv = __floats2half2_rn(f0, f1);
            B1[nt] = *(uint32_t*)&hv;
        }
        float bias0 = k1b[c0 + tg * 2],     bias1 = k1b[c0 + tg * 2 + 1];
        float bias2 = k1b[c0 + 8 + tg * 2], bias3 = k1b[c0 + 8 + tg * 2 + 1];
        __syncthreads();   // EA tile ready

        #pragma unroll
        for (int rt = 0; rt < 8; rt++) {
            uint32_t a[2];
            ldsm_x2(a, sEA + (uint32_t)(rt * 16 + lrow) * 16);
            float acc0[4] = {0.f, 0.f, 0.f, 0.f};
            float acc1[4] = {0.f, 0.f, 0.f, 0.f};
            mma16808(acc0, a[0], a[1], B1[0]);
            mma16808(acc1, a[0], a[1], B1[1]);
            int r0 = rt * 16;
            __half2 q0 = __floats2half2_rn(
                fmaxf(acc0[0] + bias0, 0.f), fmaxf(acc0[1] + bias1, 0.f));
            __half2 q1 = __floats2half2_rn(
                fmaxf(acc1[0] + bias2, 0.f), fmaxf(acc1[1] + bias3, 0.f));
            *(uint2*)&A1[(r0 + g) * ST + c0 + tg * 4] =
                make_uint2(*(uint32_t*)&q0, *(uint32_t*)&q1);
            __half2 q2 = __floats2half2_rn(
                fmaxf(acc0[2] + bias0, 0.f), fmaxf(acc0[3] + bias1, 0.f));
            __half2 q3 = __floats2half2_rn(
                fmaxf(acc1[2] + bias2, 0.f), fmaxf(acc1[3] + bias3, 0.f));
            *(uint2*)&A1[(r0 + g + 8) * ST + c0 + tg * 4] =
                make_uint2(*(uint32_t*)&q2, *(uint32_t*)&q3);
        }
    }
    __syncthreads();

    // ---- stage 2: e2 = relu(e1 @ k2_w + k2_b), 2D warp tiling ----
    {
        const int colQ = warp & 3;         // 32-col quarter
        const int rowH = warp >> 2;        // 64-row half
        const int c0 = colQ * 32;
        uint32_t B2f[64];                  // [nt*16 + ks*2 + h]
        {
            const uint4* tp = ((const uint4*)d_k2p) + (colQ * 16) * 32 + lane;
            #pragma unroll
            for (int c = 0; c < 16; c++) {
                uint4 v = tp[c * 32];
                B2f[c * 4 + 0] = v.x; B2f[c * 4 + 1] = v.y;
                B2f[c * 4 + 2] = v.z; B2f[c * 4 + 3] = v.w;
            }
        }
        float biasA[4], biasB[4];
        #pragma unroll
        for (int nt = 0; nt < 4; nt++) {
            biasA[nt] = k2b[c0 + nt * 8 + tg * 2];
            biasB[nt] = k2b[c0 + nt * 8 + tg * 2 + 1];
        }

        #pragma unroll
        for (int rt = 0; rt < 4; rt++) {
            const int r0 = rowH * 64 + rt * 16;
            float acc[4][4];
            #pragma unroll
            for (int nt = 0; nt < 4; nt++)
                acc[nt][0] = acc[nt][1] = acc[nt][2] = acc[nt][3] = 0.f;
            #pragma unroll
            for (int ks = 0; ks < 8; ks++) {
                uint32_t a[4];
                ldsm_x4(a, sA1 + ((r0 + lrow) * ST + ks * 16 + lcol) * 2);
                #pragma unroll
                for (int nt = 0; nt < 4; nt++)
                    mma16816(acc[nt], a[0], a[1], a[2], a[3],
                             B2f[nt * 16 + ks * 2], B2f[nt * 16 + ks * 2 + 1]);
            }
            uint32_t p0[4], p1[4];
            #pragma unroll
            for (int nt = 0; nt < 4; nt++) {
                __half2 h0 = __floats2half2_rn(
                    fmaxf(acc[nt][0] + biasA[nt], 0.f), fmaxf(acc[nt][1] + biasB[nt], 0.f));
                __half2 h1 = __floats2half2_rn(
                    fmaxf(acc[nt][2] + biasA[nt], 0.f), fmaxf(acc[nt][3] + biasB[nt], 0.f));
                p0[nt] = *(uint32_t*)&h0;
                p1[nt] = *(uint32_t*)&h1;
            }
            *(uint4*)&A2[(r0 + g) * ST + c0 + tg * 8] =
                make_uint4(p0[0], p0[1], p0[2], p0[3]);
            *(uint4*)&A2[(r0 + g + 8) * ST + c0 + tg * 8] =
                make_uint4(p1[0], p1[1], p1[2], p1[3]);
        }
    }
    __syncthreads();

    // ---- stage 3: W = e2 @ k3_w + k3_b -> conv-coalesced [k][o] layout ----
    // Thread's half2 (nt, row-half): o = (nt&1)*4+tg, i = warp*2+(nt>>1).
    // Store word(i,o) = (i>>2)*32 + o*4 + (i&3).
    {
        const int c0 = warp * 32;
        uint32_t B3f[64];                  // [nt*16 + ks*2 + h]
        {
            const uint4* tp = ((const uint4*)d_k3p) + (warp * 16) * 32 + lane;
            #pragma unroll
            for (int c = 0; c < 16; c++) {
                uint4 v = tp[c * 32];
                B3f[c * 4 + 0] = v.x; B3f[c * 4 + 1] = v.y;
                B3f[c * 4 + 2] = v.z; B3f[c * 4 + 3] = v.w;
            }
        }
        float biasA[4], biasB[4];
        #pragma unroll
        for (int nt = 0; nt < 4; nt++) {
            biasA[nt] = k3b[c0 + nt * 8 + tg * 2];
            biasB[nt] = k3b[c0 + nt * 8 + tg * 2 + 1];
        }

        const int W0 = (warp >> 1) * 32 + tg * 4 + (warp & 1) * 2;        // o=tg
        const int W1 = (warp >> 1) * 32 + (tg + 4) * 4 + (warp & 1) * 2;  // o=tg+4

        #pragma unroll
        for (int rt = 0; rt < 8; rt++) {
            const int r0 = rt * 16;
            float acc[4][4];
            #pragma unroll
            for (int nt = 0; nt < 4; nt++)
                acc[nt][0] = acc[nt][1] = acc[nt][2] = acc[nt][3] = 0.f;
            #pragma unroll
            for (int ks = 0; ks < 8; ks++) {
                uint32_t a[4];
                ldsm_x4(a, sA2 + ((r0 + lrow) * ST + ks * 16 + lcol) * 2);
                #pragma unroll
                for (int nt = 0; nt < 4; nt++)
                    mma16816(acc[nt], a[0], a[1], a[2], a[3],
                             B3f[nt * 16 + ks * 2], B3f[nt * 16 + ks * 2 + 1]);
            }
            uint32_t p0[4], p1[4];
            #pragma unroll
            for (int nt = 0; nt < 4; nt++) {
                __half2 h0 = __floats2half2_rn(acc[nt][0] + biasA[nt], acc[nt][1] + biasB[nt]);
                __half2 h1 = __floats2half2_rn(acc[nt][2] + biasA[nt], acc[nt][3] + biasB[nt]);
                p0[nt] = *(uint32_t*)&h0;
                p1[nt] = *(uint32_t*)&h1;
            }
            uint32_t* Wp0 = (uint32_t*)(d_W + (ebase + r0 + g) * 256);
            uint32_t* Wp1 = (uint32_t*)(d_W + (ebase + r0 + g + 8) * 256);
            stcs_v2(&Wp0[W0], p0[0], p0[2]);
            stcs_v2(&Wp0[W1], p0[1], p0[3]);
            stcs_v2(&Wp1[W0], p1[0], p1[2]);
            stcs_v2(&Wp1[W1], p1[1], p1[3]);
        }
    }
}

// msg = h[src] @ W_e ([k][o] layout), 2 edges/thread for MLP depth;
// vector scatter-add into agg[dst].
__global__ void k_conv(const void* __restrict__ ei, const float* __restrict__ hin)
{
    const int warp = threadIdx.x >> 5;
    const int lane = threadIdx.x & 31;
    const int eidx = lane >> 3;        // 0..3
    const int o    = lane & 7;         // output half2 index (cols 2o, 2o+1)
    const long long wb = (long long)blockIdx.x * 64 + warp * 8;
    const long long e0 = wb + eidx, e1 = wb + eidx + 4;

    long long src0, dst0, src1, dst1;
    if (d_is64) {
        const long long* p = (const long long*)ei;
        src0 = p[e0]; dst0 = p[EE + e0];
        src1 = p[e1]; dst1 = p[EE + e1];
    } else {
        const int* p = (const int*)ei;
        src0 = p[e0]; dst0 = p[EE + e0];
        src1 = p[e1]; dst1 = p[EE + e1];
    }

    // issue all 8 W loads + 2 h gathers up front (MLP depth 12)
    const uint4* wpa = (const uint4*)(d_W + e0 * 256);
    const uint4* wpb = (const uint4*)(d_W + e1 * 256);
    uint4 a0 = __ldcs(wpa + o),      a1 = __ldcs(wpa + 8 + o),
          a2 = __ldcs(wpa + 16 + o), a3 = __ldcs(wpa + 24 + o);
    uint4 b0 = __ldcs(wpb + o),      b1 = __ldcs(wpb + 8 + o),
          b2 = __ldcs(wpb + 16 + o), b3 = __ldcs(wpb + 24 + o);
    const float4* ha4 = (const float4*)(hin + src0 * EMB);
    const float4* hb4 = (const float4*)(hin + src1 * EMB);
    float4 ha0 = ha4[0], ha1 = ha4[1], ha2 = ha4[2], ha3 = ha4[3];
    float4 hb0 = hb4[0], hb1 = hb4[1], hb2 = hb4[2], hb3 = hb4[3];

    float hra[16] = {ha0.x,ha0.y,ha0.z,ha0.w, ha1.x,ha1.y,ha1.z,ha1.w,
                     ha2.x,ha2.y,ha2.z,ha2.w, ha3.x,ha3.y,ha3.z,ha3.w};
    float hrb[16] = {hb0.x,hb0.y,hb0.z,hb0.w, hb1.x,hb1.y,hb1.z,hb1.w,
                     hb2.x,hb2.y,hb2.z,hb2.w, hb3.x,hb3.y,hb3.z,hb3.w};
    uint32_t wva[16] = {a0.x,a0.y,a0.z,a0.w, a1.x,a1.y,a1.z,a1.w,
                        a2.x,a2.y,a2.z,a2.w, a3.x,a3.y,a3.z,a3.w};
    uint32_t wvb[16] = {b0.x,b0.y,b0.z,b0.w, b1.x,b1.y,b1.z,b1.w,
                        b2.x,b2.y,b2.z,b2.w, b3.x,b3.y,b3.z,b3.w};

    float mxa = 0.f, mya = 0.f, mxb = 0.f, myb = 0.f;
    #pragma unroll
    for (int i = 0; i < 16; i++) {
        float2 wa = __half22float2(*(__half2*)&wva[i]);   // W_e0[i][2o..2o+1]
        float2 wbv = __half22float2(*(__half2*)&wvb[i]);
        mxa = fmaf(hra[i], wa.x, mxa);
        mya = fmaf(hra[i], wa.y, mya);
        mxb = fmaf(hrb[i], wbv.x, mxb);
        myb = fmaf(hrb[i], wbv.y, myb);
    }
    float* dpa = &d_agg[dst0 * EMB + 2 * o];
    float* dpb = &d_agg[dst1 * EMB + 2 * o];
    asm volatile("red.global.add.v2.f32 [%0], {%1,%2};\n"
                 :: "l"(dpa), "f"(mxa), "f"(mya) : "memory");
    asm volatile("red.global.add.v2.f32 [%0], {%1,%2};\n"
                 :: "l"(dpb), "f"(mxb), "f"(myb) : "memory");
}

// h_out = relu(agg/denom + h_in @ root_w + conv_b); zero agg for next round
__global__ void k_update(const float* __restrict__ hin, float* __restrict__ hout,
                         const float* __restrict__ root_w, const float* __restrict__ conv_b)
{
    int t = blockIdx.x * blockDim.x + threadIdx.x;
    if (t >= NN * EMB) return;
    int n = t >> 4, o = t & 15;
    float denom = fmaxf(d_cnt[n], 1.f);
    float v = d_agg[t] / denom;
    const float* hr = hin + n * EMB;
    #pragma unroll
    for (int i = 0; i < 16; i++) v = fmaf(hr[i], root_w[i * EMB + o], v);
    v += conv_b[o];
    hout[t] = fmaxf(v, 0.f);
    d_agg[t] = 0.f;
}

__global__ void k_out(const float* __restrict__ hin,
                      const float* __restrict__ inv_w, const float* __restrict__ inv_b,
                      float* __restrict__ out)
{
    int t = blockIdx.x * blockDim.x + threadIdx.x;
    if (t >= NN * 3) return;
    int n = t / 3, f = t % 3;
    float v = inv_b[f];
    const float* hr = hin + n * EMB;
    #pragma unroll
    for (int i = 0; i < 16; i++) v = fmaf(hr[i], inv_w[i * 3 + f], v);
    out[t] = v;
}

// ---------------- launcher ----------------
extern "C" void kernel_launch(void* const* d_in, const int* in_sizes, int n_in,
                              void* d_out, int out_size)
{
    const float* x      = (const float*)d_in[0];
    const void*  ei     = d_in[1];
    const float* ea     = (const float*)d_in[2];
    const float* emb_w  = (const float*)d_in[3];
    const float* emb_b  = (const float*)d_in[4];
    const float* k1_w   = (const float*)d_in[5];
    const float* k1_b   = (const float*)d_in[6];
    const float* k2_w   = (const float*)d_in[7];
    const float* k2_b   = (const float*)d_in[8];
    const float* k3_w   = (const float*)d_in[9];
    const float* k3_b   = (const float*)d_in[10];
    const float* root_w = (const float*)d_in[11];
    const float* conv_b = (const float*)d_in[12];
    const float* inv_w  = (const float*)d_in[13];
    const float* inv_b  = (const float*)d_in[14];
    float* out = (float*)d_out;

    const int ST = KW + 8;
    const int smemBytes = (2 * 128 * ST + 128 * 8) * (int)sizeof(__half);  // 71680
    cudaFuncSetAttribute(k_mlp, cudaFuncAttributeMaxDynamicSharedMemorySize, smemBytes);

    static float* hA = nullptr;
    static float* hB = nullptr;
    if (!hA) {
        cudaGetSymbolAddress((void**)&hA, d_hA);
        cudaGetSymbolAddress((void**)&hB, d_hB);
    }

    // Launch order: setup(1), mlp(2), conv1(3)... — conv stays profiled early.
    k_setup<<<3125 + 96 + 1, 256>>>((const int*)ei, x, emb_w, emb_b, k2_w, k3_w);
    k_mlp<<<EE / 128, 256, smemBytes>>>(ei, ea, k1_w, k1_b, k2_b, k3_b);

    float* hin  = hA;
    float* hout = hB;
    for (int it = 0; it < NCONV; it++) {
        k_conv<<<EE / 64, 256>>>(ei, hin);
        k_update<<<(NN * EMB + 255) / 256, 256>>>(hin, hout, root_w, conv_b);
        float* tmp = hin; hin = hout; hout = tmp;
    }
    k_out<<<(NN * 3 + 255) / 256, 256>>>(hin, inv_w, inv_b, out);
}

// round 15
// speedup vs baseline: 1.2612x; 1.0289x over previous
#include <cuda_runtime.h>
#include <cuda_fp16.h>
#include <cstdint>

#define NN   50000
#define EE   800000
#define EMB  16
#define KW   128
#define NCONV 4

// ---------------- device scratch (no cudaMalloc allowed) ----------------
__device__ __half  d_W[(size_t)EE * 256];     // per-edge 16x16 W, fragment-permuted fp16
__device__ float   d_hA[NN * EMB];
__device__ float   d_hB[NN * EMB];
__device__ float   d_agg[NN * EMB];
__device__ float   d_cnt[NN];
__device__ __half2 d_k2p[8192];               // k2 fragments: [colQ][chunk16][lane][4]
__device__ __half2 d_k3p[16384];              // k3 fragments: [warp][chunk16][lane][4]
__device__ int     d_is64;

// ---------------- helpers ----------------
__device__ __forceinline__ void mma16816(float* c,
    uint32_t a0, uint32_t a1, uint32_t a2, uint32_t a3,
    uint32_t b0, uint32_t b1)
{
    asm volatile(
        "mma.sync.aligned.m16n8k16.row.col.f32.f16.f16.f32 "
        "{%0,%1,%2,%3},{%4,%5,%6,%7},{%8,%9},{%0,%1,%2,%3};\n"
        : "+f"(c[0]), "+f"(c[1]), "+f"(c[2]), "+f"(c[3])
        : "r"(a0), "r"(a1), "r"(a2), "r"(a3), "r"(b0), "r"(b1));
}

__device__ __forceinline__ void mma16808(float* c, uint32_t a0, uint32_t a1, uint32_t b0)
{
    asm volatile(
        "mma.sync.aligned.m16n8k8.row.col.f32.f16.f16.f32 "
        "{%0,%1,%2,%3},{%4,%5},{%6},{%0,%1,%2,%3};\n"
        : "+f"(c[0]), "+f"(c[1]), "+f"(c[2]), "+f"(c[3])
        : "r"(a0), "r"(a1), "r"(b0));
}

__device__ __forceinline__ void ldsm_x4(uint32_t* a, uint32_t saddr)
{
    asm volatile(
        "ldmatrix.sync.aligned.m8n8.x4.shared.b16 {%0,%1,%2,%3}, [%4];\n"
        : "=r"(a[0]), "=r"(a[1]), "=r"(a[2]), "=r"(a[3]) : "r"(saddr));
}

__device__ __forceinline__ void ldsm_x2(uint32_t* a, uint32_t saddr)
{
    asm volatile(
        "ldmatrix.sync.aligned.m8n8.x2.shared.b16 {%0,%1}, [%2];\n"
        : "=r"(a[0]), "=r"(a[1]) : "r"(saddr));
}

__device__ __forceinline__ void stcs_v4(void* p, uint32_t x, uint32_t y, uint32_t z, uint32_t w)
{
    asm volatile("st.global.cs.v4.b32 [%0], {%1,%2,%3,%4};\n"
                 :: "l"(p), "r"(x), "r"(y), "r"(z), "r"(w) : "memory");
}

// ---------------- kernels ----------------

// Fused setup: blocks [0,3125) h0 init + zero agg/cnt; blocks [3125,3221)
// fragment-permuted B tables; block 3221 edge-index dtype detection.
__global__ void k_setup(const int* __restrict__ ei,
                        const float* __restrict__ x,
                        const float* __restrict__ emb_w,
                        const float* __restrict__ emb_b,
                        const float* __restrict__ k2w,
                        const float* __restrict__ k3w)
{
    if (blockIdx.x < 3125) {
        int t = blockIdx.x * 256 + threadIdx.x;
        if (t >= NN * EMB) return;
        int n = t >> 4, o = t & 15;
        float v = emb_b[o];
        #pragma unroll
        for (int f = 0; f < 3; f++) v += x[n * 3 + f] * emb_w[f * EMB + o];
        d_hA[t]  = v;
        d_agg[t] = 0.f;
        if (o == 0) d_cnt[n] = 0.f;
        return;
    }
    if (blockIdx.x == 3125 + 96) {      // dtype detect
        __shared__ int anynz;
        if (threadIdx.x == 0) anynz = 0;
        __syncthreads();
        int v = ei[2 * threadIdx.x + 1];
        if (v != 0) atomicOr(&anynz, 1);
        __syncthreads();
        if (threadIdx.x == 0) d_is64 = (anynz == 0) ? 1 : 0;
        return;
    }
    int t = (blockIdx.x - 3125) * 256 + threadIdx.x;
    if (t < 8192) {            // stage-2 table: 4 colQ x 16 chunks x 32 lanes x 4
        int j = t & 3, l = (t >> 2) & 31, c = (t >> 7) & 15, cq = t >> 11;
        int q = c * 4 + j;                       // nt*16 + ks*2 + h
        int nt = q >> 4, ks = (q >> 1) & 7, h = q & 1;
        int g = l >> 2, tg = l & 3;
        int n = cq * 32 + nt * 8 + g;
        int k = ks * 16 + (tg & 1) * 8 + (h * 2 + (tg >> 1)) * 2;
        d_k2p[t] = __floats2half2_rn(k2w[k * KW + n], k2w[(k + 1) * KW + n]);
    } else if (t < 8192 + 16384) {  // stage-3 table: 8 warps x 16 chunks x 32 lanes x 4
        int t2 = t - 8192;
        int j = t2 & 3, l = (t2 >> 2) & 31, c = (t2 >> 7) & 15, w = t2 >> 11;
        int q = c * 4 + j;
        int nt = q >> 4, ks = (q >> 1) & 7, h = q & 1;
        int g = l >> 2, tg = l & 3;
        int n = w * 32 + nt * 8 + g;
        int k = (ks >> 1) * 32 + tg * 8 + ((ks & 1) * 2 + h) * 2;
        d_k3p[t2] = __floats2half2_rn(k3w[k * 256 + n], k3w[(k + 1) * 256 + n]);
    }
}

// Fused edge-MLP: 128 edges/block, all layers on tensor cores.
// Stage2 uses 2D warp tiling; A1/A2 use K-permuted layouts (64/128-bit STS).
// Stage3 writes W fragment-permuted with uint4 streaming stores.
// Stage0 also performs the scatter-mean edge counting.
__global__ __launch_bounds__(256, 2) void k_mlp(
    const void* __restrict__ ei,
    const float* __restrict__ ea,
    const float* __restrict__ k1w, const float* __restrict__ k1b,
    const float* __restrict__ k2b, const float* __restrict__ k3b)
{
    const int ST = KW + 8;                 // smem row stride in halves (272B, 16B-mult)
    extern __shared__ __half sm[];
    __half* A1 = sm;                       // e1: 128 x ST (K-permuted per 16-block)
    __half* A2 = A1 + 128 * ST;            // e2: 128 x ST (K-permuted per 32-block)
    __half* EA = A2 + 128 * ST;            // ea fp16: 128 x 8

    const int tid  = threadIdx.x;
    const int warp = tid >> 5;
    const int lane = tid & 31;
    const int g    = lane >> 2;
    const int tg   = lane & 3;
    const long long ebase = (long long)blockIdx.x * 128;

    const uint32_t sA1 = (uint32_t)__cvta_generic_to_shared(A1);
    const uint32_t sA2 = (uint32_t)__cvta_generic_to_shared(A2);
    const uint32_t sEA = (uint32_t)__cvta_generic_to_shared(EA);
    const uint32_t lrow = (lane & 15);
    const uint32_t lcol = (lane >> 4) * 8;

    // ---- stage 0: ea -> fp16 smem tile [128 x 8]; fused edge count ----
    if (tid < 128) {
        const float* er = ea + (ebase + tid) * 6;
        float a0 = er[0], a1 = er[1], a2 = er[2], a3 = er[3], a4 = er[4], a5 = er[5];
        __half2* row = (__half2*)(EA + tid * 8);
        row[0] = __floats2half2_rn(a0, a1);
        row[1] = __floats2half2_rn(a2, a3);
        row[2] = __floats2half2_rn(a4, a5);
        row[3] = __floats2half2_rn(0.f, 0.f);
        long long dst;
        if (d_is64) dst = ((const long long*)ei)[EE + ebase + tid];
        else        dst = ((const int*)ei)[EE + ebase + tid];
        atomicAdd(&d_cnt[dst], 1.f);
    }

    // ---- stage 1: e1 = relu(ea @ k1_w + k1_b) via m16n8k8 -> permuted A1 ----
    {
        const int c0 = warp * 16;
        uint32_t B1[2];
        #pragma unroll
        for (int nt = 0; nt < 2; nt++) {
            int n  = c0 + nt * 8 + g;
            int k0 = tg * 2;
            float f0 = (k0     < 6) ? k1w[k0 * KW + n]       : 0.f;
            float f1 = (k0 + 1 < 6) ? k1w[(k0 + 1) * KW + n] : 0.f;
            __half2 hv = __floats2half2_rn(f0, f1);
            B1[nt] = *(uint32_t*)&hv;
        }
        float bias0 = k1b[c0 + tg * 2],     bias1 = k1b[c0 + tg * 2 + 1];
        float bias2 = k1b[c0 + 8 + tg * 2], bias3 = k1b[c0 + 8 + tg * 2 + 1];
        __syncthreads();   // EA tile ready

        #pragma unroll
        for (int rt = 0; rt < 8; rt++) {
            uint32_t a[2];
            ldsm_x2(a, sEA + (uint32_t)(rt * 16 + lrow) * 16);
            float acc0[4] = {0.f, 0.f, 0.f, 0.f};
            float acc1[4] = {0.f, 0.f, 0.f, 0.f};
            mma16808(acc0, a[0], a[1], B1[0]);
            mma16808(acc1, a[0], a[1], B1[1]);
            int r0 = rt * 16;
            // permuted store: pos c0 + tg*4 + {0,1,2,3} <- cols {tg*2,tg*2+1,8+tg*2,8+tg*2+1}
            __half2 q0 = __floats2half2_rn(
                fmaxf(acc0[0] + bias0, 0.f), fmaxf(acc0[1] + bias1, 0.f));
            __half2 q1 = __floats2half2_rn(
                fmaxf(acc1[0] + bias2, 0.f), fmaxf(acc1[1] + bias3, 0.f));
            *(uint2*)&A1[(r0 + g) * ST + c0 + tg * 4] =
                make_uint2(*(uint32_t*)&q0, *(uint32_t*)&q1);
            __half2 q2 = __floats2half2_rn(
                fmaxf(acc0[2] + bias0, 0.f), fmaxf(acc0[3] + bias1, 0.f));
            __half2 q3 = __floats2half2_rn(
                fmaxf(acc1[2] + bias2, 0.f), fmaxf(acc1[3] + bias3, 0.f));
            *(uint2*)&A1[(r0 + g + 8) * ST + c0 + tg * 4] =
                make_uint2(*(uint32_t*)&q2, *(uint32_t*)&q3);
        }
    }
    __syncthreads();

    // ---- stage 2: e2 = relu(e1 @ k2_w + k2_b), 2D warp tiling ----
    {
        const int colQ = warp & 3;         // 32-col quarter
        const int rowH = warp >> 2;        // 64-row half
        const int c0 = colQ * 32;
        uint32_t B2f[64];                  // [nt*16 + ks*2 + h]
        {
            const uint4* tp = ((const uint4*)d_k2p) + (colQ * 16) * 32 + lane;
            #pragma unroll
            for (int c = 0; c < 16; c++) {
                uint4 v = tp[c * 32];
                B2f[c * 4 + 0] = v.x; B2f[c * 4 + 1] = v.y;
                B2f[c * 4 + 2] = v.z; B2f[c * 4 + 3] = v.w;
            }
        }
        float biasA[4], biasB[4];
        #pragma unroll
        for (int nt = 0; nt < 4; nt++) {
            biasA[nt] = k2b[c0 + nt * 8 + tg * 2];
            biasB[nt] = k2b[c0 + nt * 8 + tg * 2 + 1];
        }

        #pragma unroll
        for (int rt = 0; rt < 4; rt++) {
            const int r0 = rowH * 64 + rt * 16;
            float acc[4][4];
            #pragma unroll
            for (int nt = 0; nt < 4; nt++)
                acc[nt][0] = acc[nt][1] = acc[nt][2] = acc[nt][3] = 0.f;
            #pragma unroll
            for (int ks = 0; ks < 8; ks++) {
                uint32_t a[4];
                ldsm_x4(a, sA1 + ((r0 + lrow) * ST + ks * 16 + lcol) * 2);
                #pragma unroll
                for (int nt = 0; nt < 4; nt++)
                    mma16816(acc[nt], a[0], a[1], a[2], a[3],
                             B2f[nt * 16 + ks * 2], B2f[nt * 16 + ks * 2 + 1]);
            }
            // permuted store: pos c0 + tg*8 + nt*2 + b <- col c0 + nt*8 + tg*2 + b
            uint32_t p0[4], p1[4];
            #pragma unroll
            for (int nt = 0; nt < 4; nt++) {
                __half2 h0 = __floats2half2_rn(
                    fmaxf(acc[nt][0] + biasA[nt], 0.f), fmaxf(acc[nt][1] + biasB[nt], 0.f));
                __half2 h1 = __floats2half2_rn(
                    fmaxf(acc[nt][2] + biasA[nt], 0.f), fmaxf(acc[nt][3] + biasB[nt], 0.f));
                p0[nt] = *(uint32_t*)&h0;
                p1[nt] = *(uint32_t*)&h1;
            }
            *(uint4*)&A2[(r0 + g) * ST + c0 + tg * 8] =
                make_uint4(p0[0], p0[1], p0[2], p0[3]);
            *(uint4*)&A2[(r0 + g + 8) * ST + c0 + tg * 8] =
                make_uint4(p1[0], p1[1], p1[2], p1[3]);
        }
    }
    __syncthreads();

    // ---- stage 3: W = e2 @ k3_w + k3_b -> permuted fp16 global (128-bit cs) ----
    {
        const int c0 = warp * 32;
        uint32_t B3f[64];                  // [nt*16 + ks*2 + h]
        {
            const uint4* tp = ((const uint4*)d_k3p) + (warp * 16) * 32 + lane;
            #pragma unroll
            for (int c = 0; c < 16; c++) {
                uint4 v = tp[c * 32];
                B3f[c * 4 + 0] = v.x; B3f[c * 4 + 1] = v.y;
                B3f[c * 4 + 2] = v.z; B3f[c * 4 + 3] = v.w;
            }
        }
        float biasA[4], biasB[4];
        #pragma unroll
        for (int nt = 0; nt < 4; nt++) {
            biasA[nt] = k3b[c0 + nt * 8 + tg * 2];
            biasB[nt] = k3b[c0 + nt * 8 + tg * 2 + 1];
        }

        #pragma unroll
        for (int rt = 0; rt < 8; rt++) {
            const int r0 = rt * 16;
            float acc[4][4];
            #pragma unroll
            for (int nt = 0; nt < 4; nt++)
                acc[nt][0] = acc[nt][1] = acc[nt][2] = acc[nt][3] = 0.f;
            #pragma unroll
            for (int ks = 0; ks < 8; ks++) {
                uint32_t a[4];
                ldsm_x4(a, sA2 + ((r0 + lrow) * ST + ks * 16 + lcol) * 2);
                #pragma unroll
                for (int nt = 0; nt < 4; nt++)
                    mma16816(acc[nt], a[0], a[1], a[2], a[3],
                             B3f[nt * 16 + ks * 2], B3f[nt * 16 + ks * 2 + 1]);
            }
            // permuted W store: pos (c0 + tg*8 + nt*2 + b) holds logical col
            // (c0 + nt*8 + tg*2 + b). Per row-half one uint4.
            uint32_t p0[4], p1[4];
            #pragma unroll
            for (int nt = 0; nt < 4; nt++) {
                __half2 h0 = __floats2half2_rn(acc[nt][0] + biasA[nt], acc[nt][1] + biasB[nt]);
                __half2 h1 = __floats2half2_rn(acc[nt][2] + biasA[nt], acc[nt][3] + biasB[nt]);
                p0[nt] = *(uint32_t*)&h0;
                p1[nt] = *(uint32_t*)&h1;
            }
            __half* base0 = d_W + (ebase + r0 + g) * 256 + c0 + tg * 8;
            __half* base1 = d_W + (ebase + r0 + g + 8) * 256 + c0 + tg * 8;
            stcs_v4(base0, p0[0], p0[1], p0[2], p0[3]);
            stcs_v4(base1, p1[0], p1[1], p1[2], p1[3]);
        }
    }
}

// msg = h[src] @ W_e (fragment-permuted layout) ; vector scatter-add into agg[dst]
__global__ void k_conv(const void* __restrict__ ei, const float* __restrict__ hin)
{
    long long e = (long long)blockIdx.x * 32 + (threadIdx.x >> 3);
    int o = threadIdx.x & 7;           // output half2 index (cols 2o, 2o+1)
    if (e >= EE) return;
    long long src, dst;
    if (d_is64) {
        const long long* p = (const long long*)ei;
        src = p[e]; dst = p[EE + e];
    } else {
        const int* p = (const int*)ei;
        src = p[e]; dst = p[EE + e];
    }
    const float4* hr4 = (const float4*)(hin + src * EMB);
    float4 h0 = hr4[0], h1 = hr4[1], h2 = hr4[2], h3 = hr4[3];
    float hr[16] = {h0.x,h0.y,h0.z,h0.w, h1.x,h1.y,h1.z,h1.w,
                    h2.x,h2.y,h2.z,h2.w, h3.x,h3.y,h3.z,h3.w};
    const __half2* Wr = (const __half2*)(d_W + e * 256);
    const int oa = (o & 3) * 4 + (o >> 2);   // permutation constant for this o
    float mx = 0.f, my = 0.f;
    #pragma unroll
    for (int i = 0; i < 16; i++) {
        // inverse fragment permutation: logical col i*16+2o(+1)
        int idx = (i >> 1) * 16 + (i & 1) * 2 + oa;
        float2 wf = __half22float2(__ldcs(&Wr[idx]));
        mx = fmaf(hr[i], wf.x, mx);
        my = fmaf(hr[i], wf.y, my);
    }
    float* dp = &d_agg[dst * EMB + 2 * o];
    asm volatile("red.global.add.v2.f32 [%0], {%1,%2};\n"
                 :: "l"(dp), "f"(mx), "f"(my) : "memory");
}

// h_out = relu(agg/denom + h_in @ root_w + conv_b); zero agg for next round
__global__ void k_update(const float* __restrict__ hin, float* __restrict__ hout,
                         const float* __restrict__ root_w, const float* __restrict__ conv_b)
{
    int t = blockIdx.x * blockDim.x + threadIdx.x;
    if (t >= NN * EMB) return;
    int n = t >> 4, o = t & 15;
    float denom = fmaxf(d_cnt[n], 1.f);
    float v = d_agg[t] / denom;
    const float* hr = hin + n * EMB;
    #pragma unroll
    for (int i = 0; i < 16; i++) v = fmaf(hr[i], root_w[i * EMB + o], v);
    v += conv_b[o];
    hout[t] = fmaxf(v, 0.f);
    d_agg[t] = 0.f;
}

__global__ void k_out(const float* __restrict__ hin,
                      const float* __restrict__ inv_w, const float* __restrict__ inv_b,
                      float* __restrict__ out)
{
    int t = blockIdx.x * blockDim.x + threadIdx.x;
    if (t >= NN * 3) return;
    int n = t / 3, f = t % 3;
    float v = inv_b[f];
    const float* hr = hin + n * EMB;
    #pragma unroll
    for (int i = 0; i < 16; i++) v = fmaf(hr[i], inv_w[i * 3 + f], v);
    out[t] = v;
}

// ---------------- launcher ----------------
extern "C" void kernel_launch(void* const* d_in, const int* in_sizes, int n_in,
                              void* d_out, int out_size)
{
    const float* x      = (const float*)d_in[0];
    const void*  ei     = d_in[1];
    const float* ea     = (const float*)d_in[2];
    const float* emb_w  = (const float*)d_in[3];
    const float* emb_b  = (const float*)d_in[4];
    const float* k1_w   = (const float*)d_in[5];
    const float* k1_b   = (const float*)d_in[6];
    const float* k2_w   = (const float*)d_in[7];
    const float* k2_b   = (const float*)d_in[8];
    const float* k3_w   = (const float*)d_in[9];
    const float* k3_b   = (const float*)d_in[10];
    const float* root_w = (const float*)d_in[11];
    const float* conv_b = (const float*)d_in[12];
    const float* inv_w  = (const float*)d_in[13];
    const float* inv_b  = (const float*)d_in[14];
    float* out = (float*)d_out;

    const int ST = KW + 8;
    const int smemBytes = (2 * 128 * ST + 128 * 8) * (int)sizeof(__half);  // 71680
    cudaFuncSetAttribute(k_mlp, cudaFuncAttributeMaxDynamicSharedMemorySize, smemBytes);

    static float* hA = nullptr;
    static float* hB = nullptr;
    if (!hA) {
        cudaGetSymbolAddress((void**)&hA, d_hA);
        cudaGetSymbolAddress((void**)&hB, d_hB);
    }

    // setup(1) [init + tables + dtype-detect], mlp(2), conv/update loop, out.
    k_setup<<<3125 + 96 + 1, 256>>>((const int*)ei, x, emb_w, emb_b, k2_w, k3_w);
    k_mlp<<<EE / 128, 256, smemBytes>>>(ei, ea, k1_w, k1_b, k2_b, k3_b);

    float* hin  = hA;
    float* hout = hB;
    for (int it = 0; it < NCONV; it++) {
        k_conv<<<EE / 32, 256>>>(ei, hin);
        k_update<<<(NN * EMB + 255) / 256, 256>>>(hin, hout, root_w, conv_b);
        float* tmp = hin; hin = hout; hout = tmp;
    }
    k_out<<<(NN * 3 + 255) / 256, 256>>>(hin, inv_w, inv_b, out);
}

// round 16
// speedup vs baseline: 1.2673x; 1.0048x over previous
#include <cuda_runtime.h>
#include <cuda_fp16.h>
#include <cstdint>

#define NN   50000
#define EE   800000
#define EMB  16
#define KW   128
#define NCONV 4

// ---------------- device scratch (no cudaMalloc allowed) ----------------
__device__ __half  d_W[(size_t)EE * 256];     // per-edge 16x16 W, fragment-permuted fp16
__device__ float   d_hA[NN * EMB];
__device__ float   d_hB[NN * EMB];
__device__ float   d_agg[NN * EMB];
__device__ float   d_cnt[NN];
__device__ __half2 d_k2p[8192];               // k2 fragments: [colQ][chunk16][lane][4]
__device__ __half2 d_k3p[16384];              // k3 fragments: [warp][chunk16][lane][4]
__device__ int     d_is64;

// ---------------- helpers ----------------
__device__ __forceinline__ void mma16816(float* c,
    uint32_t a0, uint32_t a1, uint32_t a2, uint32_t a3,
    uint32_t b0, uint32_t b1)
{
    asm volatile(
        "mma.sync.aligned.m16n8k16.row.col.f32.f16.f16.f32 "
        "{%0,%1,%2,%3},{%4,%5,%6,%7},{%8,%9},{%0,%1,%2,%3};\n"
        : "+f"(c[0]), "+f"(c[1]), "+f"(c[2]), "+f"(c[3])
        : "r"(a0), "r"(a1), "r"(a2), "r"(a3), "r"(b0), "r"(b1));
}

__device__ __forceinline__ void mma16808(float* c, uint32_t a0, uint32_t a1, uint32_t b0)
{
    asm volatile(
        "mma.sync.aligned.m16n8k8.row.col.f32.f16.f16.f32 "
        "{%0,%1,%2,%3},{%4,%5},{%6},{%0,%1,%2,%3};\n"
        : "+f"(c[0]), "+f"(c[1]), "+f"(c[2]), "+f"(c[3])
        : "r"(a0), "r"(a1), "r"(b0));
}

__device__ __forceinline__ void ldsm_x4(uint32_t* a, uint32_t saddr)
{
    asm volatile(
        "ldmatrix.sync.aligned.m8n8.x4.shared.b16 {%0,%1,%2,%3}, [%4];\n"
        : "=r"(a[0]), "=r"(a[1]), "=r"(a[2]), "=r"(a[3]) : "r"(saddr));
}

__device__ __forceinline__ void ldsm_x2(uint32_t* a, uint32_t saddr)
{
    asm volatile(
        "ldmatrix.sync.aligned.m8n8.x2.shared.b16 {%0,%1}, [%2];\n"
        : "=r"(a[0]), "=r"(a[1]) : "r"(saddr));
}

__device__ __forceinline__ void stcs_v4(void* p, uint32_t x, uint32_t y, uint32_t z, uint32_t w)
{
    asm volatile("st.global.cs.v4.b32 [%0], {%1,%2,%3,%4};\n"
                 :: "l"(p), "r"(x), "r"(y), "r"(z), "r"(w) : "memory");
}

// ---------------- kernels ----------------

// Fused setup: blocks [0,3125) h0 init + zero agg/cnt; blocks [3125,3221)
// fragment-permuted B tables; block 3221 edge-index dtype detection.
__global__ void k_setup(const int* __restrict__ ei,
                        const float* __restrict__ x,
                        const float* __restrict__ emb_w,
                        const float* __restrict__ emb_b,
                        const float* __restrict__ k2w,
                        const float* __restrict__ k3w)
{
    if (blockIdx.x < 3125) {
        int t = blockIdx.x * 256 + threadIdx.x;
        if (t >= NN * EMB) return;
        int n = t >> 4, o = t & 15;
        float v = emb_b[o];
        #pragma unroll
        for (int f = 0; f < 3; f++) v += x[n * 3 + f] * emb_w[f * EMB + o];
        d_hA[t]  = v;
        d_agg[t] = 0.f;
        if (o == 0) d_cnt[n] = 0.f;
        return;
    }
    if (blockIdx.x == 3125 + 96) {      // dtype detect
        __shared__ int anynz;
        if (threadIdx.x == 0) anynz = 0;
        __syncthreads();
        int v = ei[2 * threadIdx.x + 1];
        if (v != 0) atomicOr(&anynz, 1);
        __syncthreads();
        if (threadIdx.x == 0) d_is64 = (anynz == 0) ? 1 : 0;
        return;
    }
    int t = (blockIdx.x - 3125) * 256 + threadIdx.x;
    if (t < 8192) {            // stage-2 table: 4 colQ x 16 chunks x 32 lanes x 4
        int j = t & 3, l = (t >> 2) & 31, c = (t >> 7) & 15, cq = t >> 11;
        int q = c * 4 + j;                       // nt*16 + ks*2 + h
        int nt = q >> 4, ks = (q >> 1) & 7, h = q & 1;
        int g = l >> 2, tg = l & 3;
        int n = cq * 32 + nt * 8 + g;
        int k = ks * 16 + (tg & 1) * 8 + (h * 2 + (tg >> 1)) * 2;
        d_k2p[t] = __floats2half2_rn(k2w[k * KW + n], k2w[(k + 1) * KW + n]);
    } else if (t < 8192 + 16384) {  // stage-3 table: 8 warps x 16 chunks x 32 lanes x 4
        int t2 = t - 8192;
        int j = t2 & 3, l = (t2 >> 2) & 31, c = (t2 >> 7) & 15, w = t2 >> 11;
        int q = c * 4 + j;
        int nt = q >> 4, ks = (q >> 1) & 7, h = q & 1;
        int g = l >> 2, tg = l & 3;
        int n = w * 32 + nt * 8 + g;
        int k = (ks >> 1) * 32 + tg * 8 + ((ks & 1) * 2 + h) * 2;
        d_k3p[t2] = __floats2half2_rn(k3w[k * 256 + n], k3w[(k + 1) * 256 + n]);
    }
}

// Fused edge-MLP: 128 edges/block, all layers on tensor cores.
// Stage2 uses 2D warp tiling; A1/A2 use K-permuted layouts (64/128-bit STS).
// Stage3 writes W fragment-permuted with uint4 streaming stores.
// Stage0 also performs the scatter-mean edge counting.
__global__ __launch_bounds__(256, 2) void k_mlp(
    const void* __restrict__ ei,
    const float* __restrict__ ea,
    const float* __restrict__ k1w, const float* __restrict__ k1b,
    const float* __restrict__ k2b, const float* __restrict__ k3b)
{
    const int ST = KW + 8;                 // smem row stride in halves (272B, 16B-mult)
    extern __shared__ __half sm[];
    __half* A1 = sm;                       // e1: 128 x ST (K-permuted per 16-block)
    __half* A2 = A1 + 128 * ST;            // e2: 128 x ST (K-permuted per 32-block)
    __half* EA = A2 + 128 * ST;            // ea fp16: 128 x 8

    const int tid  = threadIdx.x;
    const int warp = tid >> 5;
    const int lane = tid & 31;
    const int g    = lane >> 2;
    const int tg   = lane & 3;
    const long long ebase = (long long)blockIdx.x * 128;

    const uint32_t sA1 = (uint32_t)__cvta_generic_to_shared(A1);
    const uint32_t sA2 = (uint32_t)__cvta_generic_to_shared(A2);
    const uint32_t sEA = (uint32_t)__cvta_generic_to_shared(EA);
    const uint32_t lrow = (lane & 15);
    const uint32_t lcol = (lane >> 4) * 8;

    // ---- stage 0: ea -> fp16 smem tile [128 x 8]; fused edge count ----
    if (tid < 128) {
        const float* er = ea + (ebase + tid) * 6;
        float a0 = er[0], a1 = er[1], a2 = er[2], a3 = er[3], a4 = er[4], a5 = er[5];
        __half2* row = (__half2*)(EA + tid * 8);
        row[0] = __floats2half2_rn(a0, a1);
        row[1] = __floats2half2_rn(a2, a3);
        row[2] = __floats2half2_rn(a4, a5);
        row[3] = __floats2half2_rn(0.f, 0.f);
        long long dst;
        if (d_is64) dst = ((const long long*)ei)[EE + ebase + tid];
        else        dst = ((const int*)ei)[EE + ebase + tid];
        atomicAdd(&d_cnt[dst], 1.f);
    }

    // ---- stage 1: e1 = relu(ea @ k1_w + k1_b) via m16n8k8 -> permuted A1 ----
    {
        const int c0 = warp * 16;
        uint32_t B1[2];
        #pragma unroll
        for (int nt = 0; nt < 2; nt++) {
            int n  = c0 + nt * 8 + g;
            int k0 = tg * 2;
            float f0 = (k0     < 6) ? k1w[k0 * KW + n]       : 0.f;
            float f1 = (k0 + 1 < 6) ? k1w[(k0 + 1) * KW + n] : 0.f;
            __half2 hv = __floats2half2_rn(f0, f1);
            B1[nt] = *(uint32_t*)&hv;
        }
        float bias0 = k1b[c0 + tg * 2],     bias1 = k1b[c0 + tg * 2 + 1];
        float bias2 = k1b[c0 + 8 + tg * 2], bias3 = k1b[c0 + 8 + tg * 2 + 1];
        __syncthreads();   // EA tile ready

        #pragma unroll
        for (int rt = 0; rt < 8; rt++) {
            uint32_t a[2];
            ldsm_x2(a, sEA + (uint32_t)(rt * 16 + lrow) * 16);
            float acc0[4] = {0.f, 0.f, 0.f, 0.f};
            float acc1[4] = {0.f, 0.f, 0.f, 0.f};
            mma16808(acc0, a[0], a[1], B1[0]);
            mma16808(acc1, a[0], a[1], B1[1]);
            int r0 = rt * 16;
            // permuted store: pos c0 + tg*4 + {0,1,2,3} <- cols {tg*2,tg*2+1,8+tg*2,8+tg*2+1}
            __half2 q0 = __floats2half2_rn(
                fmaxf(acc0[0] + bias0, 0.f), fmaxf(acc0[1] + bias1, 0.f));
            __half2 q1 = __floats2half2_rn(
                fmaxf(acc1[0] + bias2, 0.f), fmaxf(acc1[1] + bias3, 0.f));
            *(uint2*)&A1[(r0 + g) * ST + c0 + tg * 4] =
                make_uint2(*(uint32_t*)&q0, *(uint32_t*)&q1);
            __half2 q2 = __floats2half2_rn(
                fmaxf(acc0[2] + bias0, 0.f), fmaxf(acc0[3] + bias1, 0.f));
            __half2 q3 = __floats2half2_rn(
                fmaxf(acc1[2] + bias2, 0.f), fmaxf(acc1[3] + bias3, 0.f));
            *(uint2*)&A1[(r0 + g + 8) * ST + c0 + tg * 4] =
                make_uint2(*(uint32_t*)&q2, *(uint32_t*)&q3);
        }
    }
    __syncthreads();

    // ---- stage 2: e2 = relu(e1 @ k2_w + k2_b), 2D warp tiling ----
    {
        const int colQ = warp & 3;         // 32-col quarter
        const int rowH = warp >> 2;        // 64-row half
        const int c0 = colQ * 32;
        uint32_t B2f[64];                  // [nt*16 + ks*2 + h]
        {
            const uint4* tp = ((const uint4*)d_k2p) + (colQ * 16) * 32 + lane;
            #pragma unroll
            for (int c = 0; c < 16; c++) {
                uint4 v = tp[c * 32];
                B2f[c * 4 + 0] = v.x; B2f[c * 4 + 1] = v.y;
                B2f[c * 4 + 2] = v.z; B2f[c * 4 + 3] = v.w;
            }
        }
        float biasA[4], biasB[4];
        #pragma unroll
        for (int nt = 0; nt < 4; nt++) {
            biasA[nt] = k2b[c0 + nt * 8 + tg * 2];
            biasB[nt] = k2b[c0 + nt * 8 + tg * 2 + 1];
        }

        #pragma unroll
        for (int rt = 0; rt < 4; rt++) {
            const int r0 = rowH * 64 + rt * 16;
            float acc[4][4];
            #pragma unroll
            for (int nt = 0; nt < 4; nt++)
                acc[nt][0] = acc[nt][1] = acc[nt][2] = acc[nt][3] = 0.f;
            #pragma unroll
            for (int ks = 0; ks < 8; ks++) {
                uint32_t a[4];
                ldsm_x4(a, sA1 + ((r0 + lrow) * ST + ks * 16 + lcol) * 2);
                #pragma unroll
                for (int nt = 0; nt < 4; nt++)
                    mma16816(acc[nt], a[0], a[1], a[2], a[3],
                             B2f[nt * 16 + ks * 2], B2f[nt * 16 + ks * 2 + 1]);
            }
            // permuted store: pos c0 + tg*8 + nt*2 + b <- col c0 + nt*8 + tg*2 + b
            uint32_t p0[4], p1[4];
            #pragma unroll
            for (int nt = 0; nt < 4; nt++) {
                __half2 h0 = __floats2half2_rn(
                    fmaxf(acc[nt][0] + biasA[nt], 0.f), fmaxf(acc[nt][1] + biasB[nt], 0.f));
                __half2 h1 = __floats2half2_rn(
                    fmaxf(acc[nt][2] + biasA[nt], 0.f), fmaxf(acc[nt][3] + biasB[nt], 0.f));
                p0[nt] = *(uint32_t*)&h0;
                p1[nt] = *(uint32_t*)&h1;
            }
            *(uint4*)&A2[(r0 + g) * ST + c0 + tg * 8] =
                make_uint4(p0[0], p0[1], p0[2], p0[3]);
            *(uint4*)&A2[(r0 + g + 8) * ST + c0 + tg * 8] =
                make_uint4(p1[0], p1[1], p1[2], p1[3]);
        }
    }
    __syncthreads();

    // ---- stage 3: W = e2 @ k3_w + k3_b -> permuted fp16 global (128-bit cs) ----
    {
        const int c0 = warp * 32;
        uint32_t B3f[64];                  // [nt*16 + ks*2 + h]
        {
            const uint4* tp = ((const uint4*)d_k3p) + (warp * 16) * 32 + lane;
            #pragma unroll
            for (int c = 0; c < 16; c++) {
                uint4 v = tp[c * 32];
                B3f[c * 4 + 0] = v.x; B3f[c * 4 + 1] = v.y;
                B3f[c * 4 + 2] = v.z; B3f[c * 4 + 3] = v.w;
            }
        }
        float biasA[4], biasB[4];
        #pragma unroll
        for (int nt = 0; nt < 4; nt++) {
            biasA[nt] = k3b[c0 + nt * 8 + tg * 2];
            biasB[nt] = k3b[c0 + nt * 8 + tg * 2 + 1];
        }

        #pragma unroll
        for (int rt = 0; rt < 8; rt++) {
            const int r0 = rt * 16;
            float acc[4][4];
            #pragma unroll
            for (int nt = 0; nt < 4; nt++)
                acc[nt][0] = acc[nt][1] = acc[nt][2] = acc[nt][3] = 0.f;
            #pragma unroll
            for (int ks = 0; ks < 8; ks++) {
                uint32_t a[4];
                ldsm_x4(a, sA2 + ((r0 + lrow) * ST + ks * 16 + lcol) * 2);
                #pragma unroll
                for (int nt = 0; nt < 4; nt++)
                    mma16816(acc[nt], a[0], a[1], a[2], a[3],
                             B3f[nt * 16 + ks * 2], B3f[nt * 16 + ks * 2 + 1]);
            }
            // permuted W store: pos (c0 + tg*8 + nt*2 + b) holds logical col
            // (c0 + nt*8 + tg*2 + b). Per row-half one uint4.
            uint32_t p0[4], p1[4];
            #pragma unroll
            for (int nt = 0; nt < 4; nt++) {
                __half2 h0 = __floats2half2_rn(acc[nt][0] + biasA[nt], acc[nt][1] + biasB[nt]);
                __half2 h1 = __floats2half2_rn(acc[nt][2] + biasA[nt], acc[nt][3] + biasB[nt]);
                p0[nt] = *(uint32_t*)&h0;
                p1[nt] = *(uint32_t*)&h1;
            }
            __half* base0 = d_W + (ebase + r0 + g) * 256 + c0 + tg * 8;
            __half* base1 = d_W + (ebase + r0 + g + 8) * 256 + c0 + tg * 8;
            stcs_v4(base0, p0[0], p0[1], p0[2], p0[3]);
            stcs_v4(base1, p1[0], p1[1], p1[2], p1[3]);
        }
    }
}

// msg = h[src] @ W_e (fragment-permuted layout) ; vector scatter-add into agg[dst]
__global__ void k_conv(const void* __restrict__ ei, const float* __restrict__ hin)
{
    long long e = (long long)blockIdx.x * 32 + (threadIdx.x >> 3);
    int o = threadIdx.x & 7;           // output half2 index (cols 2o, 2o+1)
    if (e >= EE) return;
    long long src, dst;
    if (d_is64) {
        const long long* p = (const long long*)ei;
        src = p[e]; dst = p[EE + e];
    } else {
        const int* p = (const int*)ei;
        src = p[e]; dst = p[EE + e];
    }
    const float4* hr4 = (const float4*)(hin + src * EMB);
    float4 h0 = hr4[0], h1 = hr4[1], h2 = hr4[2], h3 = hr4[3];
    float hr[16] = {h0.x,h0.y,h0.z,h0.w, h1.x,h1.y,h1.z,h1.w,
                    h2.x,h2.y,h2.z,h2.w, h3.x,h3.y,h3.z,h3.w};
    const __half2* Wr = (const __half2*)(d_W + e * 256);
    const int oa = (o & 3) * 4 + (o >> 2);   // permutation constant for this o
    float mx = 0.f, my = 0.f;
    #pragma unroll
    for (int i = 0; i < 16; i++) {
        // inverse fragment permutation: logical col i*16+2o(+1)
        int idx = (i >> 1) * 16 + (i & 1) * 2 + oa;
        float2 wf = __half22float2(__ldcs(&Wr[idx]));
        mx = fmaf(hr[i], wf.x, mx);
        my = fmaf(hr[i], wf.y, my);
    }
    float* dp = &d_agg[dst * EMB + 2 * o];
    asm volatile("red.global.add.v2.f32 [%0], {%1,%2};\n"
                 :: "l"(dp), "f"(mx), "f"(my) : "memory");
}

// h_out = relu(agg/denom + h_in @ root_w + conv_b).
// Non-final iters: write hout, zero agg. Final iter (last=1): instead compute
// out = h @ inv_w + inv_b via 16-lane butterfly reductions (no hout/agg traffic).
__global__ void k_update(const float* __restrict__ hin, float* __restrict__ hout,
                         const float* __restrict__ root_w, const float* __restrict__ conv_b,
                         const float* __restrict__ inv_w, const float* __restrict__ inv_b,
                         float* __restrict__ out, int last)
{
    int t = blockIdx.x * blockDim.x + threadIdx.x;
    if (t >= NN * EMB) return;
    int n = t >> 4, o = t & 15;
    float denom = fmaxf(d_cnt[n], 1.f);
    float v = d_agg[t] / denom;
    const float* hr = hin + n * EMB;
    #pragma unroll
    for (int i = 0; i < 16; i++) v = fmaf(hr[i], root_w[i * EMB + o], v);
    v += conv_b[o];
    v = fmaxf(v, 0.f);
    if (!last) {
        hout[t] = v;
        d_agg[t] = 0.f;
        return;
    }
    // final: out[n][f] = sum_o v_o * inv_w[o*3+f] + inv_b[f]
    #pragma unroll
    for (int f = 0; f < 3; f++) {
        float p = v * inv_w[o * 3 + f];
        p += __shfl_xor_sync(0xFFFFFFFFu, p, 8);
        p += __shfl_xor_sync(0xFFFFFFFFu, p, 4);
        p += __shfl_xor_sync(0xFFFFFFFFu, p, 2);
        p += __shfl_xor_sync(0xFFFFFFFFu, p, 1);
        if (o == 0) out[n * 3 + f] = p + inv_b[f];
    }
}

// ---------------- launcher ----------------
extern "C" void kernel_launch(void* const* d_in, const int* in_sizes, int n_in,
                              void* d_out, int out_size)
{
    const float* x      = (const float*)d_in[0];
    const void*  ei     = d_in[1];
    const float* ea     = (const float*)d_in[2];
    const float* emb_w  = (const float*)d_in[3];
    const float* emb_b  = (const float*)d_in[4];
    const float* k1_w   = (const float*)d_in[5];
    const float* k1_b   = (const float*)d_in[6];
    const float* k2_w   = (const float*)d_in[7];
    const float* k2_b   = (const float*)d_in[8];
    const float* k3_w   = (const float*)d_in[9];
    const float* k3_b   = (const float*)d_in[10];
    const float* root_w = (const float*)d_in[11];
    const float* conv_b = (const float*)d_in[12];
    const float* inv_w  = (const float*)d_in[13];
    const float* inv_b  = (const float*)d_in[14];
    float* out = (float*)d_out;

    const int ST = KW + 8;
    const int smemBytes = (2 * 128 * ST + 128 * 8) * (int)sizeof(__half);  // 71680
    cudaFuncSetAttribute(k_mlp, cudaFuncAttributeMaxDynamicSharedMemorySize, smemBytes);

    static float* hA = nullptr;
    static float* hB = nullptr;
    if (!hA) {
        cudaGetSymbolAddress((void**)&hA, d_hA);
        cudaGetSymbolAddress((void**)&hB, d_hB);
    }

    // setup(1) [init + tables + dtype-detect], mlp(2), conv/update loop
    // (final update fuses the inverse-embedding output projection).
    k_setup<<<3125 + 96 + 1, 256>>>((const int*)ei, x, emb_w, emb_b, k2_w, k3_w);
    k_mlp<<<EE / 128, 256, smemBytes>>>(ei, ea, k1_w, k1_b, k2_b, k3_b);

    float* hin  = hA;
    float* hout = hB;
    for (int it = 0; it < NCONV; it++) {
        int last = (it == NCONV - 1) ? 1 : 0;
        k_conv<<<EE / 32, 256>>>(ei, hin);
        k_update<<<(NN * EMB + 255) / 256, 256>>>(hin, hout, root_w, conv_b,
                                                  inv_w, inv_b, out, last);
        float* tmp = hin; hin = hout; hout = tmp;
    }
}